// round 4
// baseline (speedup 1.0000x reference)
#include <cuda_runtime.h>

#define NN 100000
#define NE 1000000
#define D  128

// ---------------- scratch (device globals; no allocations allowed) ----------
__device__ int   g_cnt[NN + 1];
__device__ int   g_off[NN + 2];
__device__ int   g_pos[NN];
__device__ int   g_srcs[NE];
__device__ int   g_part[128];
__device__ float g_mean[(size_t)NN * D];
__device__ float g_h   [(size_t)NN * D];
__device__ float g_x1  [(size_t)NN * D];
__device__ float g_x2  [(size_t)NN * D];
__device__ float g_P   [(size_t)NN * 16];
__device__ float g_Q   [(size_t)NN * 16];

// ---------------- packed f32x2 helpers --------------------------------------
__device__ __forceinline__ unsigned long long pk2(float lo, float hi) {
    unsigned long long r;
    asm("mov.b64 %0, {%1, %2};" : "=l"(r) : "f"(lo), "f"(hi));
    return r;
}
__device__ __forceinline__ void upk2(unsigned long long v, float &lo, float &hi) {
    asm("mov.b64 {%0, %1}, %2;" : "=f"(lo), "=f"(hi) : "l"(v));
}
__device__ __forceinline__ void ffma2(unsigned long long &d, unsigned long long a,
                                      unsigned long long b) {
    asm("fma.rn.f32x2 %0, %1, %2, %0;" : "+l"(d) : "l"(a), "l"(b));
}

// ---------------- CSR build (edge_index is int32: JAX x64 disabled) ----------
__global__ void k_zero_cnt() {
    int i = blockIdx.x * blockDim.x + threadIdx.x;
    if (i <= NN) g_cnt[i] = 0;
}

__global__ void k_count(const int* __restrict__ ei) {
    int e = blockIdx.x * blockDim.x + threadIdx.x;
    if (e < NE) {
        unsigned d = (unsigned)ei[NE + e];
        if (d < NN) atomicAdd(&g_cnt[d], 1);
    }
}

__global__ void k_scan_block() {   // per-block exclusive scan of g_cnt -> g_off
    __shared__ int sh[1024];
    int i = blockIdx.x * 1024 + threadIdx.x;
    int v = (i < NN) ? g_cnt[i] : 0;
    sh[threadIdx.x] = v;
    __syncthreads();
    for (int off = 1; off < 1024; off <<= 1) {
        int t = (threadIdx.x >= off) ? sh[threadIdx.x - off] : 0;
        __syncthreads();
        sh[threadIdx.x] += t;
        __syncthreads();
    }
    if (i < NN) g_off[i] = sh[threadIdx.x] - v;   // exclusive
    if (threadIdx.x == 1023) g_part[blockIdx.x] = sh[1023];
}

__global__ void k_scan_add() {
    __shared__ int s_base;
    int b = blockIdx.x;
    if (threadIdx.x == 0) {
        int s = 0;
        for (int j = 0; j < b; j++) s += g_part[j];
        s_base = s;
    }
    __syncthreads();
    int i = b * 1024 + threadIdx.x;
    if (i < NN) {
        int o = g_off[i] + s_base;
        g_off[i] = o;
        g_pos[i] = o;
    }
    if (i == 0) g_off[NN] = NE;
}

__global__ void k_fill(const int* __restrict__ ei) {
    int e = blockIdx.x * blockDim.x + threadIdx.x;
    if (e < NE) {
        unsigned d = (unsigned)ei[NE + e];
        if (d < NN) {
            int p = atomicAdd(&g_pos[d], 1);
            if (p >= 0 && p < NE) g_srcs[p] = ei[e];
        }
    }
}

// ---------------- mean aggregation: one warp per node ------------------------
__global__ void k_aggregate(const float* __restrict__ xin) {
    int n = blockIdx.x * (blockDim.x >> 5) + (threadIdx.x >> 5);
    if (n >= NN) return;
    int lane = threadIdx.x & 31;
    int beg = g_off[n], end = g_off[n + 1];
    float ax = 0.f, ay = 0.f, az = 0.f, aw = 0.f;
    for (int t = beg; t < end; t++) {
        unsigned s = (unsigned)g_srcs[t];
        if (s >= NN) continue;
        float4 v = *reinterpret_cast<const float4*>(xin + (size_t)s * D + lane * 4);
        ax += v.x; ay += v.y; az += v.z; aw += v.w;
    }
    int c = end - beg;
    float inv = 1.0f / (float)(c > 0 ? c : 1);
    float4 o; o.x = ax * inv; o.y = ay * inv; o.z = az * inv; o.w = aw * inv;
    *reinterpret_cast<float4*>(g_mean + (size_t)n * D + lane * 4) = o;
}

// ---------------- fused dual GEMM: C = relu(A0*W0^T + A1*W1^T + b) ----------
// A0,A1: [nrows,128] (stride 128). W0,W1: [128, sW] row-major, 128 cols used.
// BM=128, BN=128, BK=16, 128 threads, thread tile 16(m) x 8(n), f32x2 packed.
#define BK  16
#define BMP 132

__device__ __forceinline__ void gemm_ldg(
    int kb, int row0, int am, int akq, int tid, int nrows,
    const float* __restrict__ A0, const float* __restrict__ A1,
    const float* __restrict__ W0, const float* __restrict__ W1,
    int sW0, int sW1, float4* areg, float4* breg)
{
    const float* Asrc; const float* Wsrc; int sw; int kcol;
    if (kb < 8) { Asrc = A0; Wsrc = W0; sw = sW0; kcol = kb * BK; }
    else        { Asrc = A1; Wsrc = W1; sw = sW1; kcol = (kb - 8) * BK; }
    #pragma unroll
    for (int i = 0; i < 4; i++) {
        int r = row0 + am + 32 * i;
        areg[i] = (r < nrows)
            ? *reinterpret_cast<const float4*>(Asrc + (size_t)r * D + kcol + akq)
            : make_float4(0.f, 0.f, 0.f, 0.f);
    }
    #pragma unroll
    for (int i = 0; i < 4; i++)
        breg[i] = *reinterpret_cast<const float4*>(Wsrc + (size_t)tid * sw + kcol + i * 4);
}

__global__ void __launch_bounds__(128, 2) k_gemm_dual(
    const float* __restrict__ A0, const float* __restrict__ A1,
    const float* __restrict__ W0, const float* __restrict__ W1,
    int sW0, int sW1,
    const float* __restrict__ bias, float* __restrict__ C, int nrows)
{
    __shared__ __align__(16) float As[BK][BMP]; // [k][m], pad: 2-way store conflict only
    __shared__ __align__(16) float Bs[BK][128]; // [k][n], conflict-free both ways

    int tid  = threadIdx.x;
    int row0 = blockIdx.x * 128;
    int mg   = tid >> 4;            // 0..7
    int ng   = tid & 15;            // 0..15
    int m0   = mg * 16;
    int n0a  = ng * 4;
    int n0b  = 64 + n0a;
    int am   = tid >> 2;            // A load row within tile
    int akq  = (tid & 3) * 4;       // A load k offset

    unsigned long long acc[8][8];
    #pragma unroll
    for (int i = 0; i < 8; i++)
        #pragma unroll
        for (int j = 0; j < 8; j++) acc[i][j] = 0ULL;

    float4 areg[4], breg[4];

    gemm_ldg(0, row0, am, akq, tid, nrows, A0, A1, W0, W1, sW0, sW1, areg, breg);
    #pragma unroll
    for (int i = 0; i < 4; i++) {
        As[akq + 0][am + 32 * i] = areg[i].x;
        As[akq + 1][am + 32 * i] = areg[i].y;
        As[akq + 2][am + 32 * i] = areg[i].z;
        As[akq + 3][am + 32 * i] = areg[i].w;
        Bs[i * 4 + 0][tid] = breg[i].x;
        Bs[i * 4 + 1][tid] = breg[i].y;
        Bs[i * 4 + 2][tid] = breg[i].z;
        Bs[i * 4 + 3][tid] = breg[i].w;
    }
    __syncthreads();

    for (int kb = 0; kb < 16; kb++) {
        if (kb + 1 < 16)
            gemm_ldg(kb + 1, row0, am, akq, tid, nrows, A0, A1, W0, W1, sW0, sW1, areg, breg);

        #pragma unroll
        for (int k = 0; k < BK; k++) {
            ulonglong2 u01 = *reinterpret_cast<const ulonglong2*>(&As[k][m0]);
            ulonglong2 u23 = *reinterpret_cast<const ulonglong2*>(&As[k][m0 + 4]);
            ulonglong2 u45 = *reinterpret_cast<const ulonglong2*>(&As[k][m0 + 8]);
            ulonglong2 u67 = *reinterpret_cast<const ulonglong2*>(&As[k][m0 + 12]);
            float4 b0 = *reinterpret_cast<const float4*>(&Bs[k][n0a]);
            float4 b1 = *reinterpret_cast<const float4*>(&Bs[k][n0b]);
            unsigned long long ap[8] = {u01.x, u01.y, u23.x, u23.y,
                                        u45.x, u45.y, u67.x, u67.y};
            unsigned long long bp[8];
            bp[0] = pk2(b0.x, b0.x); bp[1] = pk2(b0.y, b0.y);
            bp[2] = pk2(b0.z, b0.z); bp[3] = pk2(b0.w, b0.w);
            bp[4] = pk2(b1.x, b1.x); bp[5] = pk2(b1.y, b1.y);
            bp[6] = pk2(b1.z, b1.z); bp[7] = pk2(b1.w, b1.w);
            #pragma unroll
            for (int i = 0; i < 8; i++)
                #pragma unroll
                for (int j = 0; j < 8; j++)
                    ffma2(acc[i][j], ap[i], bp[j]);
        }
        __syncthreads();
        if (kb + 1 < 16) {
            #pragma unroll
            for (int i = 0; i < 4; i++) {
                As[akq + 0][am + 32 * i] = areg[i].x;
                As[akq + 1][am + 32 * i] = areg[i].y;
                As[akq + 2][am + 32 * i] = areg[i].z;
                As[akq + 3][am + 32 * i] = areg[i].w;
                Bs[i * 4 + 0][tid] = breg[i].x;
                Bs[i * 4 + 1][tid] = breg[i].y;
                Bs[i * 4 + 2][tid] = breg[i].z;
                Bs[i * 4 + 3][tid] = breg[i].w;
            }
            __syncthreads();
        }
    }

    float4 ba = *reinterpret_cast<const float4*>(bias + n0a);
    float4 bb = *reinterpret_cast<const float4*>(bias + n0b);
    #pragma unroll
    for (int i = 0; i < 8; i++) {
        int r = row0 + m0 + 2 * i;
        float la[4], ha[4], lb[4], hb[4];
        upk2(acc[i][0], la[0], ha[0]); upk2(acc[i][1], la[1], ha[1]);
        upk2(acc[i][2], la[2], ha[2]); upk2(acc[i][3], la[3], ha[3]);
        upk2(acc[i][4], lb[0], hb[0]); upk2(acc[i][5], lb[1], hb[1]);
        upk2(acc[i][6], lb[2], hb[2]); upk2(acc[i][7], lb[3], hb[3]);
        if (r < nrows) {
            float4 oa, ob;
            oa.x = fmaxf(la[0] + ba.x, 0.f); oa.y = fmaxf(la[1] + ba.y, 0.f);
            oa.z = fmaxf(la[2] + ba.z, 0.f); oa.w = fmaxf(la[3] + ba.w, 0.f);
            ob.x = fmaxf(lb[0] + bb.x, 0.f); ob.y = fmaxf(lb[1] + bb.y, 0.f);
            ob.z = fmaxf(lb[2] + bb.z, 0.f); ob.w = fmaxf(lb[3] + bb.w, 0.f);
            *reinterpret_cast<float4*>(C + (size_t)r * D + n0a) = oa;
            *reinterpret_cast<float4*>(C + (size_t)r * D + n0b) = ob;
        }
        if (r + 1 < nrows) {
            float4 oa, ob;
            oa.x = fmaxf(ha[0] + ba.x, 0.f); oa.y = fmaxf(ha[1] + ba.y, 0.f);
            oa.z = fmaxf(ha[2] + ba.z, 0.f); oa.w = fmaxf(ha[3] + ba.w, 0.f);
            ob.x = fmaxf(hb[0] + bb.x, 0.f); ob.y = fmaxf(hb[1] + bb.y, 0.f);
            ob.z = fmaxf(hb[2] + bb.z, 0.f); ob.w = fmaxf(hb[3] + bb.w, 0.f);
            *reinterpret_cast<float4*>(C + (size_t)(r + 1) * D + n0a) = oa;
            *reinterpret_cast<float4*>(C + (size_t)(r + 1) * D + n0b) = ob;
        }
    }
}

// ---------------- P/Q: N x 16 projections of x2 with W_o halves --------------
__global__ void __launch_bounds__(256) k_pq(const float* __restrict__ x,
                                            const float* __restrict__ Wo) {
    __shared__ __align__(16) float sw[16 * 256];
    for (int i = threadIdx.x; i < 4096; i += 256) sw[i] = Wo[i];
    __syncthreads();
    int n = blockIdx.x * 256 + threadIdx.x;
    if (n >= NN) return;
    const float4* xr = reinterpret_cast<const float4*>(x + (size_t)n * D);
    float accP[16], accQ[16];
    #pragma unroll
    for (int j = 0; j < 16; j++) { accP[j] = 0.f; accQ[j] = 0.f; }
    #pragma unroll 4
    for (int k4 = 0; k4 < 32; k4++) {
        float4 xv = xr[k4];
        #pragma unroll
        for (int j = 0; j < 16; j++) {
            float4 wa = *reinterpret_cast<const float4*>(&sw[j * 256 + k4 * 4]);
            float4 wb = *reinterpret_cast<const float4*>(&sw[j * 256 + 128 + k4 * 4]);
            accP[j] += xv.x * wa.x + xv.y * wa.y + xv.z * wa.z + xv.w * wa.w;
            accQ[j] += xv.x * wb.x + xv.y * wb.y + xv.z * wb.z + xv.w * wb.w;
        }
    }
    #pragma unroll
    for (int j = 0; j < 16; j++) {
        g_P[(size_t)n * 16 + j] = accP[j];
        g_Q[(size_t)n * 16 + j] = accQ[j];
    }
}

// ---------------- edge head: out[e] = P[src] + Q[dst] + b_o ------------------
__global__ void k_edge(const int* __restrict__ ei,
                       const float* __restrict__ bo, float* __restrict__ out) {
    int t = blockIdx.x * blockDim.x + threadIdx.x;
    if (t >= NE * 4) return;
    int e = t >> 2, q = t & 3;
    unsigned s = (unsigned)ei[e];
    unsigned d = (unsigned)ei[NE + e];
    float4 p  = (s < NN) ? reinterpret_cast<const float4*>(g_P)[(size_t)s * 4 + q]
                         : make_float4(0.f, 0.f, 0.f, 0.f);
    float4 qv = (d < NN) ? reinterpret_cast<const float4*>(g_Q)[(size_t)d * 4 + q]
                         : make_float4(0.f, 0.f, 0.f, 0.f);
    float4 b = reinterpret_cast<const float4*>(bo)[q];
    float4 o;
    o.x = p.x + qv.x + b.x; o.y = p.y + qv.y + b.y;
    o.z = p.z + qv.z + b.z; o.w = p.w + qv.w + b.w;
    reinterpret_cast<float4*>(out)[(size_t)e * 4 + q] = o;
}

// ---------------- launch -----------------------------------------------------
extern "C" void kernel_launch(void* const* d_in, const int* in_sizes, int n_in,
                              void* d_out, int out_size) {
    const float* x    = (const float*)d_in[0];
    const int*   ei   = (const int*)d_in[1];     // int32: JAX x64 is disabled
    const float* W_l0 = (const float*)d_in[2];
    const float* b_l0 = (const float*)d_in[3];
    const float* W_r0 = (const float*)d_in[4];
    const float* W_l1 = (const float*)d_in[5];
    const float* b_l1 = (const float*)d_in[6];
    const float* W_r1 = (const float*)d_in[7];
    const float* W_c  = (const float*)d_in[8];
    const float* b_c  = (const float*)d_in[9];
    const float* W_o  = (const float*)d_in[10];
    const float* b_o  = (const float*)d_in[11];
    float*       out  = (float*)d_out;

    float *p_mean, *p_h, *p_x1, *p_x2;
    cudaGetSymbolAddress((void**)&p_mean, g_mean);
    cudaGetSymbolAddress((void**)&p_h,    g_h);
    cudaGetSymbolAddress((void**)&p_x1,   g_x1);
    cudaGetSymbolAddress((void**)&p_x2,   g_x2);

    const int SCAN_NB = (NN + 1023) / 1024;
    const int GB = (NN + 127) / 128;

    // CSR build (order within a bucket is arrival-order; sums within fp tolerance)
    k_zero_cnt<<<(NN + 256) / 256, 256>>>();
    k_count<<<(NE + 255) / 256, 256>>>(ei);
    k_scan_block<<<SCAN_NB, 1024>>>();
    k_scan_add<<<SCAN_NB, 1024>>>();
    k_fill<<<(NE + 255) / 256, 256>>>(ei);

    // layer 0
    k_aggregate<<<(NN + 7) / 8, 256>>>(x);
    k_gemm_dual<<<GB, 128>>>(p_mean, x,   W_l0, W_r0,      128, 128, b_l0, p_h,  NN);
    k_gemm_dual<<<GB, 128>>>(x,      p_h, W_c,  W_c + 128, 256, 256, b_c,  p_x1, NN);

    // layer 1
    k_aggregate<<<(NN + 7) / 8, 256>>>(p_x1);
    k_gemm_dual<<<GB, 128>>>(p_mean, p_x1, W_l1, W_r1,      128, 128, b_l1, p_h,  NN);
    k_gemm_dual<<<GB, 128>>>(p_x1,   p_h,  W_c,  W_c + 128, 256, 256, b_c,  p_x2, NN);

    // edge head via linearity: out = P[src] + Q[dst] + b_o
    k_pq<<<(NN + 255) / 256, 256>>>(p_x2, W_o);
    k_edge<<<(4 * NE + 255) / 256, 256>>>(ei, b_o, out);
}

// round 7
// speedup vs baseline: 1.0055x; 1.0055x over previous
#include <cuda_runtime.h>
#include <cuda_bf16.h>
#include <cstdint>

#define NN 100000
#define NE 1000000
#define D  128

// ---------------- scratch (device globals; no allocations allowed) ----------
__device__ int   g_cnt[NN + 1];
__device__ int   g_off[NN + 2];
__device__ int   g_pos[NN];
__device__ int   g_srcs[NE];
__device__ int   g_part[128];
__device__ float g_mean[(size_t)NN * D];
__device__ float g_h   [(size_t)NN * D];
__device__ float g_x1  [(size_t)NN * D];
__device__ float g_x2  [(size_t)NN * D];
__device__ float g_P   [(size_t)NN * 16];
__device__ float g_Q   [(size_t)NN * 16];

// ---------------- helpers ----------------------------------------------------
__device__ __forceinline__ uint32_t smem_u32(const void* p) {
    uint32_t a;
    asm("{ .reg .u64 t; cvta.to.shared.u64 t, %1; cvt.u32.u64 %0, t; }"
        : "=r"(a) : "l"(p));
    return a;
}
__device__ __forceinline__ uint32_t pkbf(float lo, float hi) {
    uint32_t d;  // bits[15:0]=bf16(lo), bits[31:16]=bf16(hi)
    asm("cvt.rn.bf16x2.f32 %0, %1, %2;" : "=r"(d) : "f"(hi), "f"(lo));
    return d;
}
__device__ __forceinline__ void ldsm4(uint32_t* r, uint32_t addr) {
    asm volatile("ldmatrix.sync.aligned.m8n8.x4.shared.b16 {%0,%1,%2,%3}, [%4];"
                 : "=r"(r[0]), "=r"(r[1]), "=r"(r[2]), "=r"(r[3]) : "r"(addr));
}
__device__ __forceinline__ void mma_bf16(float* d, const uint32_t* a,
                                         const uint32_t* b) {
    asm volatile(
        "mma.sync.aligned.m16n8k16.row.col.f32.bf16.bf16.f32 "
        "{%0,%1,%2,%3}, {%4,%5,%6,%7}, {%8,%9}, {%0,%1,%2,%3};"
        : "+f"(d[0]), "+f"(d[1]), "+f"(d[2]), "+f"(d[3])
        : "r"(a[0]), "r"(a[1]), "r"(a[2]), "r"(a[3]), "r"(b[0]), "r"(b[1]));
}

// ---------------- CSR build (edge_index is int32: JAX x64 disabled) ----------
__global__ void k_zero_cnt() {
    int i = blockIdx.x * blockDim.x + threadIdx.x;
    if (i <= NN) g_cnt[i] = 0;
}

__global__ void k_count(const int* __restrict__ ei) {
    int e = blockIdx.x * blockDim.x + threadIdx.x;
    if (e < NE) {
        unsigned d = (unsigned)ei[NE + e];
        if (d < NN) atomicAdd(&g_cnt[d], 1);
    }
}

__global__ void k_scan_block() {   // per-block exclusive scan of g_cnt -> g_off
    __shared__ int sh[1024];
    int i = blockIdx.x * 1024 + threadIdx.x;
    int v = (i < NN) ? g_cnt[i] : 0;
    sh[threadIdx.x] = v;
    __syncthreads();
    for (int off = 1; off < 1024; off <<= 1) {
        int t = (threadIdx.x >= off) ? sh[threadIdx.x - off] : 0;
        __syncthreads();
        sh[threadIdx.x] += t;
        __syncthreads();
    }
    if (i < NN) g_off[i] = sh[threadIdx.x] - v;   // exclusive
    if (threadIdx.x == 1023) g_part[blockIdx.x] = sh[1023];
}

__global__ void k_scan_add() {
    __shared__ int s_base;
    int b = blockIdx.x;
    if (threadIdx.x == 0) {
        int s = 0;
        for (int j = 0; j < b; j++) s += g_part[j];
        s_base = s;
    }
    __syncthreads();
    int i = b * 1024 + threadIdx.x;
    if (i < NN) {
        int o = g_off[i] + s_base;
        g_off[i] = o;
        g_pos[i] = o;
    }
    if (i == 0) g_off[NN] = NE;
}

__global__ void k_fill(const int* __restrict__ ei) {
    int e = blockIdx.x * blockDim.x + threadIdx.x;
    if (e < NE) {
        unsigned d = (unsigned)ei[NE + e];
        if (d < NN) {
            int p = atomicAdd(&g_pos[d], 1);
            if (p >= 0 && p < NE) g_srcs[p] = ei[e];
        }
    }
}

// ---------------- mean aggregation: one warp per node ------------------------
__global__ void k_aggregate(const float* __restrict__ xin) {
    int n = blockIdx.x * (blockDim.x >> 5) + (threadIdx.x >> 5);
    if (n >= NN) return;
    int lane = threadIdx.x & 31;
    int beg = g_off[n], end = g_off[n + 1];
    float ax = 0.f, ay = 0.f, az = 0.f, aw = 0.f;
    for (int t = beg; t < end; t++) {
        unsigned s = (unsigned)g_srcs[t];
        if (s >= NN) continue;
        float4 v = *reinterpret_cast<const float4*>(xin + (size_t)s * D + lane * 4);
        ax += v.x; ay += v.y; az += v.z; aw += v.w;
    }
    int c = end - beg;
    float inv = 1.0f / (float)(c > 0 ? c : 1);
    float4 o; o.x = ax * inv; o.y = ay * inv; o.z = az * inv; o.w = aw * inv;
    *reinterpret_cast<float4*>(g_mean + (size_t)n * D + lane * 4) = o;
}

// ---------------- warp-mma dual GEMM: C = relu(A0*W0^T + A1*W1^T + b) -------
// fp32 via split-bf16 x3 (Ah*Bh + Ah*Bl + Al*Bh), fp32 accumulation in HMMA.
// BM=BN=128, 256 threads (8 warps, warp tile 32m x 64n), K in 4 chunks of 64.
// SMEM bf16 tiles, row stride 144B (72 halves) -> ldmatrix conflict-free.
#define SA_H   0
#define SA_L   18432
#define SB_H   36864
#define SB_L   55296
#define SM_TOT 73728

__device__ __forceinline__ void conv32(const float* __restrict__ src, bool valid,
                                       char* hp, char* lp) {
    #pragma unroll
    for (int i = 0; i < 4; i++) {
        float4 v0, v1;
        if (valid) {
            v0 = *reinterpret_cast<const float4*>(src + i * 8);
            v1 = *reinterpret_cast<const float4*>(src + i * 8 + 4);
        } else {
            v0 = make_float4(0.f, 0.f, 0.f, 0.f); v1 = v0;
        }
        uint4 H, L;
        H.x = pkbf(v0.x, v0.y);
        H.y = pkbf(v0.z, v0.w);
        H.z = pkbf(v1.x, v1.y);
        H.w = pkbf(v1.z, v1.w);
        L.x = pkbf(v0.x - __uint_as_float(H.x << 16),
                   v0.y - __uint_as_float(H.x & 0xFFFF0000u));
        L.y = pkbf(v0.z - __uint_as_float(H.y << 16),
                   v0.w - __uint_as_float(H.y & 0xFFFF0000u));
        L.z = pkbf(v1.x - __uint_as_float(H.z << 16),
                   v1.y - __uint_as_float(H.z & 0xFFFF0000u));
        L.w = pkbf(v1.z - __uint_as_float(H.w << 16),
                   v1.w - __uint_as_float(H.w & 0xFFFF0000u));
        *reinterpret_cast<uint4*>(hp + i * 16) = H;
        *reinterpret_cast<uint4*>(lp + i * 16) = L;
    }
}

__global__ void __launch_bounds__(256) k_gemm_mma(
    const float* __restrict__ A0, const float* __restrict__ A1,
    const float* __restrict__ W0, const float* __restrict__ W1,
    int sW0, int sW1, const float* __restrict__ bias,
    float* __restrict__ C, int nrows)
{
    extern __shared__ __align__(16) char sm[];
    uint32_t smb = smem_u32(sm);
    int tid = threadIdx.x, lane = tid & 31, wid = tid >> 5;
    int row0 = blockIdx.x * 128;
    int m0 = (wid >> 1) * 32;
    int n0 = (wid & 1) * 64;

    // ldmatrix per-lane offsets (tile t = lane/8, row rr = lane%8)
    int t = lane >> 3, rr = lane & 7;
    uint32_t aoff = (uint32_t)((((t & 1) * 8 + rr) * 144) + (t >> 1) * 16);
    uint32_t boff = (uint32_t)((((t >> 1) * 8 + rr) * 144) + (t & 1) * 16);

    float acc[2][8][4];
    #pragma unroll
    for (int i = 0; i < 2; i++)
        #pragma unroll
        for (int j = 0; j < 8; j++)
            #pragma unroll
            for (int q = 0; q < 4; q++) acc[i][j][q] = 0.f;

    int lr = tid >> 1, lh = tid & 1;   // loader: row 0..127, half 0/1

    for (int cs = 0; cs < 4; cs++) {
        const float* Asrc = (cs < 2) ? A0 : A1;
        const float* Wsrc = (cs < 2) ? W0 : W1;
        int sw = (cs < 2) ? sW0 : sW1;
        int kb = (cs & 1) * 64;

        int gr = row0 + lr;
        conv32(Asrc + (size_t)gr * D + kb + lh * 32, gr < nrows,
               sm + SA_H + lr * 144 + lh * 64, sm + SA_L + lr * 144 + lh * 64);
        conv32(Wsrc + (size_t)lr * sw + kb + lh * 32, true,
               sm + SB_H + lr * 144 + lh * 64, sm + SB_L + lr * 144 + lh * 64);
        __syncthreads();

        #pragma unroll
        for (int term = 0; term < 3; term++) {
            uint32_t ab = smb + ((term == 2) ? SA_L : SA_H);
            uint32_t bb = smb + ((term == 1) ? SB_L : SB_H);
            #pragma unroll
            for (int ks = 0; ks < 4; ks++) {
                uint32_t a0[4], a1[4], bf[4][4];
                ldsm4(a0, ab + (uint32_t)(m0 * 144) + ks * 32 + aoff);
                ldsm4(a1, ab + (uint32_t)((m0 + 16) * 144) + ks * 32 + aoff);
                #pragma unroll
                for (int nb = 0; nb < 4; nb++)
                    ldsm4(bf[nb], bb + (uint32_t)((n0 + nb * 16) * 144) + ks * 32 + boff);
                #pragma unroll
                for (int nb = 0; nb < 4; nb++) {
                    mma_bf16(acc[0][nb * 2 + 0], a0, &bf[nb][0]);
                    mma_bf16(acc[0][nb * 2 + 1], a0, &bf[nb][2]);
                    mma_bf16(acc[1][nb * 2 + 0], a1, &bf[nb][0]);
                    mma_bf16(acc[1][nb * 2 + 1], a1, &bf[nb][2]);
                }
            }
        }
        __syncthreads();
    }

    // epilogue: d-frag lane map: c0,c1 -> (m=l/4, n=2*(l%4)+{0,1}); c2,c3 -> m+8
    #pragma unroll
    for (int mi = 0; mi < 2; mi++) {
        int gr0 = row0 + m0 + mi * 16 + (lane >> 2);
        #pragma unroll
        for (int f = 0; f < 8; f++) {
            int col = n0 + f * 8 + (lane & 3) * 2;
            float2 bv = *reinterpret_cast<const float2*>(bias + col);
            if (gr0 < nrows) {
                float2 o;
                o.x = fmaxf(acc[mi][f][0] + bv.x, 0.f);
                o.y = fmaxf(acc[mi][f][1] + bv.y, 0.f);
                *reinterpret_cast<float2*>(C + (size_t)gr0 * D + col) = o;
            }
            if (gr0 + 8 < nrows) {
                float2 o;
                o.x = fmaxf(acc[mi][f][2] + bv.x, 0.f);
                o.y = fmaxf(acc[mi][f][3] + bv.y, 0.f);
                *reinterpret_cast<float2*>(C + (size_t)(gr0 + 8) * D + col) = o;
            }
        }
    }
}

// ---------------- P/Q: N x 16 projections of x2 with W_o halves --------------
__global__ void __launch_bounds__(256) k_pq(const float* __restrict__ x,
                                            const float* __restrict__ Wo) {
    __shared__ __align__(16) float sw[16 * 256];
    for (int i = threadIdx.x; i < 4096; i += 256) sw[i] = Wo[i];
    __syncthreads();
    int n = blockIdx.x * 256 + threadIdx.x;
    if (n >= NN) return;
    const float4* xr = reinterpret_cast<const float4*>(x + (size_t)n * D);
    float accP[16], accQ[16];
    #pragma unroll
    for (int j = 0; j < 16; j++) { accP[j] = 0.f; accQ[j] = 0.f; }
    #pragma unroll 4
    for (int k4 = 0; k4 < 32; k4++) {
        float4 xv = xr[k4];
        #pragma unroll
        for (int j = 0; j < 16; j++) {
            float4 wa = *reinterpret_cast<const float4*>(&sw[j * 256 + k4 * 4]);
            float4 wb = *reinterpret_cast<const float4*>(&sw[j * 256 + 128 + k4 * 4]);
            accP[j] += xv.x * wa.x + xv.y * wa.y + xv.z * wa.z + xv.w * wa.w;
            accQ[j] += xv.x * wb.x + xv.y * wb.y + xv.z * wb.z + xv.w * wb.w;
        }
    }
    #pragma unroll
    for (int j = 0; j < 16; j++) {
        g_P[(size_t)n * 16 + j] = accP[j];
        g_Q[(size_t)n * 16 + j] = accQ[j];
    }
}

// ---------------- edge head: out[e] = P[src] + Q[dst] + b_o ------------------
__global__ void k_edge(const int* __restrict__ ei,
                       const float* __restrict__ bo, float* __restrict__ out) {
    int t = blockIdx.x * blockDim.x + threadIdx.x;
    if (t >= NE * 4) return;
    int e = t >> 2, q = t & 3;
    unsigned s = (unsigned)ei[e];
    unsigned d = (unsigned)ei[NE + e];
    float4 p  = (s < NN) ? reinterpret_cast<const float4*>(g_P)[(size_t)s * 4 + q]
                         : make_float4(0.f, 0.f, 0.f, 0.f);
    float4 qv = (d < NN) ? reinterpret_cast<const float4*>(g_Q)[(size_t)d * 4 + q]
                         : make_float4(0.f, 0.f, 0.f, 0.f);
    float4 b = reinterpret_cast<const float4*>(bo)[q];
    float4 o;
    o.x = p.x + qv.x + b.x; o.y = p.y + qv.y + b.y;
    o.z = p.z + qv.z + b.z; o.w = p.w + qv.w + b.w;
    reinterpret_cast<float4*>(out)[(size_t)e * 4 + q] = o;
}

// ---------------- launch -----------------------------------------------------
extern "C" void kernel_launch(void* const* d_in, const int* in_sizes, int n_in,
                              void* d_out, int out_size) {
    const float* x    = (const float*)d_in[0];
    const int*   ei   = (const int*)d_in[1];     // int32: JAX x64 is disabled
    const float* W_l0 = (const float*)d_in[2];
    const float* b_l0 = (const float*)d_in[3];
    const float* W_r0 = (const float*)d_in[4];
    const float* W_l1 = (const float*)d_in[5];
    const float* b_l1 = (const float*)d_in[6];
    const float* W_r1 = (const float*)d_in[7];
    const float* W_c  = (const float*)d_in[8];
    const float* b_c  = (const float*)d_in[9];
    const float* W_o  = (const float*)d_in[10];
    const float* b_o  = (const float*)d_in[11];
    float*       out  = (float*)d_out;

    float *p_mean, *p_h, *p_x1, *p_x2;
    cudaGetSymbolAddress((void**)&p_mean, g_mean);
    cudaGetSymbolAddress((void**)&p_h,    g_h);
    cudaGetSymbolAddress((void**)&p_x1,   g_x1);
    cudaGetSymbolAddress((void**)&p_x2,   g_x2);

    cudaFuncSetAttribute(k_gemm_mma,
                         cudaFuncAttributeMaxDynamicSharedMemorySize, SM_TOT);

    const int SCAN_NB = (NN + 1023) / 1024;
    const int GB = (NN + 127) / 128;

    // CSR build (order within a bucket is arrival-order; sums within fp tolerance)
    k_zero_cnt<<<(NN + 256) / 256, 256>>>();
    k_count<<<(NE + 255) / 256, 256>>>(ei);
    k_scan_block<<<SCAN_NB, 1024>>>();
    k_scan_add<<<SCAN_NB, 1024>>>();
    k_fill<<<(NE + 255) / 256, 256>>>(ei);

    // layer 0
    k_aggregate<<<(NN + 7) / 8, 256>>>(x);
    k_gemm_mma<<<GB, 256, SM_TOT>>>(p_mean, x,   W_l0, W_r0,      128, 128, b_l0, p_h,  NN);
    k_gemm_mma<<<GB, 256, SM_TOT>>>(x,      p_h, W_c,  W_c + 128, 256, 256, b_c,  p_x1, NN);

    // layer 1
    k_aggregate<<<(NN + 7) / 8, 256>>>(p_x1);
    k_gemm_mma<<<GB, 256, SM_TOT>>>(p_mean, p_x1, W_l1, W_r1,      128, 128, b_l1, p_h,  NN);
    k_gemm_mma<<<GB, 256, SM_TOT>>>(p_x1,   p_h,  W_c,  W_c + 128, 256, 256, b_c,  p_x2, NN);

    // edge head via linearity: out = P[src] + Q[dst] + b_o
    k_pq<<<(NN + 255) / 256, 256>>>(p_x2, W_o);
    k_edge<<<(4 * NE + 255) / 256, 256>>>(ei, b_o, out);
}

// round 8
// speedup vs baseline: 2.3225x; 2.3097x over previous
#include <cuda_runtime.h>
#include <cuda_fp16.h>
#include <cstdint>

#define NN 100000
#define NE 1000000
#define D  128

// ---------------- scratch (device globals; no allocations allowed) ----------
__device__ int    g_cnt[NN + 1];
__device__ int    g_off[NN + 2];
__device__ int    g_pos[NN];
__device__ int    g_srcs[NE];
__device__ int    g_part[128];
__device__ __half g_xh  [(size_t)NN * D];   // fp16 copy of input x
__device__ __half g_meanh[(size_t)NN * D];
__device__ __half g_hh  [(size_t)NN * D];
__device__ __half g_x1h [(size_t)NN * D];
__device__ __half g_x2h [(size_t)NN * D];
__device__ float  g_P   [(size_t)NN * 16];
__device__ float  g_Q   [(size_t)NN * 16];

// ---------------- helpers ----------------------------------------------------
__device__ __forceinline__ uint32_t smem_u32(const void* p) {
    uint32_t a;
    asm("{ .reg .u64 t; cvta.to.shared.u64 t, %1; cvt.u32.u64 %0, t; }"
        : "=r"(a) : "l"(p));
    return a;
}
__device__ __forceinline__ uint32_t pkh(float lo, float hi) {
    uint32_t d;  // bits[15:0]=f16(lo), bits[31:16]=f16(hi)
    asm("cvt.rn.f16x2.f32 %0, %1, %2;" : "=r"(d) : "f"(hi), "f"(lo));
    return d;
}
__device__ __forceinline__ void ldsm4(uint32_t* r, uint32_t addr) {
    asm volatile("ldmatrix.sync.aligned.m8n8.x4.shared.b16 {%0,%1,%2,%3}, [%4];"
                 : "=r"(r[0]), "=r"(r[1]), "=r"(r[2]), "=r"(r[3]) : "r"(addr));
}
__device__ __forceinline__ void mma_f16(float* d, const uint32_t* a,
                                        const uint32_t* b) {
    asm volatile(
        "mma.sync.aligned.m16n8k16.row.col.f32.f16.f16.f32 "
        "{%0,%1,%2,%3}, {%4,%5,%6,%7}, {%8,%9}, {%0,%1,%2,%3};"
        : "+f"(d[0]), "+f"(d[1]), "+f"(d[2]), "+f"(d[3])
        : "r"(a[0]), "r"(a[1]), "r"(a[2]), "r"(a[3]), "r"(b[0]), "r"(b[1]));
}

// ---------------- fp32 -> fp16 input conversion ------------------------------
__global__ void k_tohalf(const float* __restrict__ x) {
    int i = blockIdx.x * blockDim.x + threadIdx.x;   // over NN*32 float4s
    if (i < NN * 32) {
        float4 v = reinterpret_cast<const float4*>(x)[i];
        uint2 h;
        h.x = pkh(v.x, v.y);
        h.y = pkh(v.z, v.w);
        reinterpret_cast<uint2*>(g_xh)[i] = h;
    }
}

// ---------------- CSR build (edge_index is int32: JAX x64 disabled) ----------
__global__ void k_zero_cnt() {
    int i = blockIdx.x * blockDim.x + threadIdx.x;
    if (i <= NN) g_cnt[i] = 0;
}

__global__ void k_count(const int* __restrict__ ei) {
    int e = blockIdx.x * blockDim.x + threadIdx.x;
    if (e < NE) {
        unsigned d = (unsigned)ei[NE + e];
        if (d < NN) atomicAdd(&g_cnt[d], 1);
    }
}

__global__ void k_scan_block() {   // per-block exclusive scan of g_cnt -> g_off
    __shared__ int sh[1024];
    int i = blockIdx.x * 1024 + threadIdx.x;
    int v = (i < NN) ? g_cnt[i] : 0;
    sh[threadIdx.x] = v;
    __syncthreads();
    for (int off = 1; off < 1024; off <<= 1) {
        int t = (threadIdx.x >= off) ? sh[threadIdx.x - off] : 0;
        __syncthreads();
        sh[threadIdx.x] += t;
        __syncthreads();
    }
    if (i < NN) g_off[i] = sh[threadIdx.x] - v;   // exclusive
    if (threadIdx.x == 1023) g_part[blockIdx.x] = sh[1023];
}

__global__ void k_scan_add() {   // parallel scan over block partials
    __shared__ int sp[128];
    int b = blockIdx.x;
    int nb = gridDim.x;
    if (threadIdx.x < 128)
        sp[threadIdx.x] = (threadIdx.x < nb) ? g_part[threadIdx.x] : 0;
    __syncthreads();
    for (int off = 1; off < 128; off <<= 1) {
        int t = 0;
        if (threadIdx.x < 128 && threadIdx.x >= off) t = sp[threadIdx.x - off];
        __syncthreads();
        if (threadIdx.x < 128) sp[threadIdx.x] += t;
        __syncthreads();
    }
    int s_base = (b == 0) ? 0 : sp[b - 1];
    int i = b * 1024 + threadIdx.x;
    if (i < NN) {
        int o = g_off[i] + s_base;
        g_off[i] = o;
        g_pos[i] = o;
    }
    if (i == 0) g_off[NN] = NE;
}

__global__ void k_fill(const int* __restrict__ ei) {
    int e = blockIdx.x * blockDim.x + threadIdx.x;
    if (e < NE) {
        unsigned d = (unsigned)ei[NE + e];
        if (d < NN) {
            int p = atomicAdd(&g_pos[d], 1);
            if (p >= 0 && p < NE) g_srcs[p] = ei[e];
        }
    }
}

// ---------------- mean aggregation (fp16 rows): one warp per node ------------
__global__ void k_aggregate(const __half* __restrict__ xin,
                            __half* __restrict__ mout) {
    int n = blockIdx.x * (blockDim.x >> 5) + (threadIdx.x >> 5);
    if (n >= NN) return;
    int lane = threadIdx.x & 31;
    int beg = g_off[n], end = g_off[n + 1];
    float ax = 0.f, ay = 0.f, az = 0.f, aw = 0.f;
    for (int t = beg; t < end; t++) {
        unsigned s = (unsigned)g_srcs[t];
        if (s >= NN) continue;
        uint2 v = *reinterpret_cast<const uint2*>(xin + (size_t)s * D + lane * 4);
        __half2 h0 = *reinterpret_cast<__half2*>(&v.x);
        __half2 h1 = *reinterpret_cast<__half2*>(&v.y);
        float2 f0 = __half22float2(h0), f1 = __half22float2(h1);
        ax += f0.x; ay += f0.y; az += f1.x; aw += f1.y;
    }
    int c = end - beg;
    float inv = 1.0f / (float)(c > 0 ? c : 1);
    uint2 o;
    o.x = pkh(ax * inv, ay * inv);
    o.y = pkh(az * inv, aw * inv);
    *reinterpret_cast<uint2*>(mout + (size_t)n * D + lane * 4) = o;
}

// ---------------- fp16 dual GEMM: C = relu(A0*W0^T + A1*W1^T + b) -----------
// A0,A1: fp16 [nrows,128]. W0,W1: fp32 row-major [128, sW] (128 cols used).
// BM=BN=128, 256 threads (8 warps, warp tile 32m x 64n), 2 phases of K=128.
// SMEM fp16 tiles, row stride 272B -> ldmatrix conflict-free.
#define SROW   272
#define SA_OFF 0
#define SB_OFF 34816
#define SM_TOT 69632

__global__ void __launch_bounds__(256, 2) k_gemm_h(
    const __half* __restrict__ A0, const __half* __restrict__ A1,
    const float* __restrict__ W0, const float* __restrict__ W1,
    int sW0, int sW1, const float* __restrict__ bias,
    __half* __restrict__ C, int nrows)
{
    extern __shared__ __align__(16) char sm[];
    uint32_t smb = smem_u32(sm);
    int tid = threadIdx.x, lane = tid & 31, wid = tid >> 5;
    int row0 = blockIdx.x * 128;
    int m0 = (wid >> 1) * 32;
    int n0 = (wid & 1) * 64;

    int t = lane >> 3, rr = lane & 7;
    uint32_t aoff = (uint32_t)((lane & 15) * SROW + (lane >> 4) * 16);
    uint32_t boff = (uint32_t)((((t >> 1) * 8 + rr) * SROW) + (t & 1) * 16);

    float acc[2][8][4];
    #pragma unroll
    for (int i = 0; i < 2; i++)
        #pragma unroll
        for (int j = 0; j < 8; j++)
            #pragma unroll
            for (int q = 0; q < 4; q++) acc[i][j][q] = 0.f;

    for (int cs = 0; cs < 2; cs++) {
        const __half* Asrc = cs ? A1 : A0;
        const float*  Wsrc = cs ? W1 : W0;
        int sw = cs ? sW1 : sW0;

        // A tile: 128 rows x 128 halves, straight 16B copies
        #pragma unroll
        for (int i = 0; i < 8; i++) {
            int idx = tid + i * 256;          // 0..2047
            int r = idx >> 4, c = idx & 15;
            int gr = row0 + r;
            uint4 v = (gr < nrows)
                ? *reinterpret_cast<const uint4*>(Asrc + (size_t)gr * D + c * 8)
                : make_uint4(0u, 0u, 0u, 0u);
            *reinterpret_cast<uint4*>(sm + SA_OFF + r * SROW + c * 16) = v;
        }
        // B tile: 128 rows x 128 floats -> fp16
        #pragma unroll
        for (int i = 0; i < 16; i++) {
            int idx = tid + i * 256;          // 0..4095
            int r = idx >> 5, c4 = idx & 31;
            float4 v = *reinterpret_cast<const float4*>(Wsrc + (size_t)r * sw + c4 * 4);
            uint2 h;
            h.x = pkh(v.x, v.y);
            h.y = pkh(v.z, v.w);
            *reinterpret_cast<uint2*>(sm + SB_OFF + r * SROW + c4 * 8) = h;
        }
        __syncthreads();

        #pragma unroll
        for (int ks = 0; ks < 8; ks++) {
            uint32_t a0[4], a1[4], bf[4][4];
            ldsm4(a0, smb + SA_OFF + (uint32_t)(m0 * SROW) + ks * 32 + aoff);
            ldsm4(a1, smb + SA_OFF + (uint32_t)((m0 + 16) * SROW) + ks * 32 + aoff);
            #pragma unroll
            for (int nb = 0; nb < 4; nb++)
                ldsm4(bf[nb], smb + SB_OFF + (uint32_t)((n0 + nb * 16) * SROW)
                              + ks * 32 + boff);
            #pragma unroll
            for (int nb = 0; nb < 4; nb++) {
                mma_f16(acc[0][nb * 2 + 0], a0, &bf[nb][0]);
                mma_f16(acc[0][nb * 2 + 1], a0, &bf[nb][2]);
                mma_f16(acc[1][nb * 2 + 0], a1, &bf[nb][0]);
                mma_f16(acc[1][nb * 2 + 1], a1, &bf[nb][2]);
            }
        }
        __syncthreads();
    }

    // epilogue: bias + relu + fp16 store
    #pragma unroll
    for (int mi = 0; mi < 2; mi++) {
        int gr0 = row0 + m0 + mi * 16 + (lane >> 2);
        #pragma unroll
        for (int f = 0; f < 8; f++) {
            int col = n0 + f * 8 + (lane & 3) * 2;
            float2 bv = *reinterpret_cast<const float2*>(bias + col);
            if (gr0 < nrows) {
                uint32_t h = pkh(fmaxf(acc[mi][f][0] + bv.x, 0.f),
                                 fmaxf(acc[mi][f][1] + bv.y, 0.f));
                *reinterpret_cast<uint32_t*>(C + (size_t)gr0 * D + col) = h;
            }
            if (gr0 + 8 < nrows) {
                uint32_t h = pkh(fmaxf(acc[mi][f][2] + bv.x, 0.f),
                                 fmaxf(acc[mi][f][3] + bv.y, 0.f));
                *reinterpret_cast<uint32_t*>(C + (size_t)(gr0 + 8) * D + col) = h;
            }
        }
    }
}

// ---------------- P/Q: N x 16 projections of x2 (fp16) with W_o halves ------
__global__ void __launch_bounds__(256) k_pq(const __half* __restrict__ x,
                                            const float* __restrict__ Wo) {
    __shared__ __align__(16) float sw[16 * 256];
    for (int i = threadIdx.x; i < 4096; i += 256) sw[i] = Wo[i];
    __syncthreads();
    int n = blockIdx.x * 256 + threadIdx.x;
    if (n >= NN) return;
    const uint4* xr = reinterpret_cast<const uint4*>(x + (size_t)n * D);
    float accP[16], accQ[16];
    #pragma unroll
    for (int j = 0; j < 16; j++) { accP[j] = 0.f; accQ[j] = 0.f; }
    #pragma unroll 2
    for (int k8 = 0; k8 < 16; k8++) {
        uint4 hv = xr[k8];
        float xv[8];
        {
            float2 f0 = __half22float2(*reinterpret_cast<__half2*>(&hv.x));
            float2 f1 = __half22float2(*reinterpret_cast<__half2*>(&hv.y));
            float2 f2 = __half22float2(*reinterpret_cast<__half2*>(&hv.z));
            float2 f3 = __half22float2(*reinterpret_cast<__half2*>(&hv.w));
            xv[0] = f0.x; xv[1] = f0.y; xv[2] = f1.x; xv[3] = f1.y;
            xv[4] = f2.x; xv[5] = f2.y; xv[6] = f3.x; xv[7] = f3.y;
        }
        #pragma unroll
        for (int j = 0; j < 16; j++) {
            const float* wa = &sw[j * 256 + k8 * 8];
            const float* wb = &sw[j * 256 + 128 + k8 * 8];
            #pragma unroll
            for (int q = 0; q < 8; q++) {
                accP[j] += xv[q] * wa[q];
                accQ[j] += xv[q] * wb[q];
            }
        }
    }
    #pragma unroll
    for (int j = 0; j < 16; j++) {
        g_P[(size_t)n * 16 + j] = accP[j];
        g_Q[(size_t)n * 16 + j] = accQ[j];
    }
}

// ---------------- edge head: out[e] = P[src] + Q[dst] + b_o ------------------
__global__ void k_edge(const int* __restrict__ ei,
                       const float* __restrict__ bo, float* __restrict__ out) {
    int t = blockIdx.x * blockDim.x + threadIdx.x;
    if (t >= NE * 4) return;
    int e = t >> 2, q = t & 3;
    unsigned s = (unsigned)ei[e];
    unsigned d = (unsigned)ei[NE + e];
    float4 p  = (s < NN) ? reinterpret_cast<const float4*>(g_P)[(size_t)s * 4 + q]
                         : make_float4(0.f, 0.f, 0.f, 0.f);
    float4 qv = (d < NN) ? reinterpret_cast<const float4*>(g_Q)[(size_t)d * 4 + q]
                         : make_float4(0.f, 0.f, 0.f, 0.f);
    float4 b = reinterpret_cast<const float4*>(bo)[q];
    float4 o;
    o.x = p.x + qv.x + b.x; o.y = p.y + qv.y + b.y;
    o.z = p.z + qv.z + b.z; o.w = p.w + qv.w + b.w;
    reinterpret_cast<float4*>(out)[(size_t)e * 4 + q] = o;
}

// ---------------- launch -----------------------------------------------------
extern "C" void kernel_launch(void* const* d_in, const int* in_sizes, int n_in,
                              void* d_out, int out_size) {
    const float* x    = (const float*)d_in[0];
    const int*   ei   = (const int*)d_in[1];     // int32: JAX x64 is disabled
    const float* W_l0 = (const float*)d_in[2];
    const float* b_l0 = (const float*)d_in[3];
    const float* W_r0 = (const float*)d_in[4];
    const float* W_l1 = (const float*)d_in[5];
    const float* b_l1 = (const float*)d_in[6];
    const float* W_r1 = (const float*)d_in[7];
    const float* W_c  = (const float*)d_in[8];
    const float* b_c  = (const float*)d_in[9];
    const float* W_o  = (const float*)d_in[10];
    const float* b_o  = (const float*)d_in[11];
    float*       out  = (float*)d_out;

    __half *p_xh, *p_mean, *p_h, *p_x1, *p_x2;
    cudaGetSymbolAddress((void**)&p_xh,   g_xh);
    cudaGetSymbolAddress((void**)&p_mean, g_meanh);
    cudaGetSymbolAddress((void**)&p_h,    g_hh);
    cudaGetSymbolAddress((void**)&p_x1,   g_x1h);
    cudaGetSymbolAddress((void**)&p_x2,   g_x2h);

    cudaFuncSetAttribute(k_gemm_h,
                         cudaFuncAttributeMaxDynamicSharedMemorySize, SM_TOT);

    const int SCAN_NB = (NN + 1023) / 1024;
    const int GB = (NN + 127) / 128;

    // input -> fp16, CSR build
    k_tohalf<<<(NN * 32 + 255) / 256, 256>>>(x);
    k_zero_cnt<<<(NN + 256) / 256, 256>>>();
    k_count<<<(NE + 255) / 256, 256>>>(ei);
    k_scan_block<<<SCAN_NB, 1024>>>();
    k_scan_add<<<SCAN_NB, 1024>>>();
    k_fill<<<(NE + 255) / 256, 256>>>(ei);

    // layer 0
    k_aggregate<<<(NN + 7) / 8, 256>>>(p_xh, p_mean);
    k_gemm_h<<<GB, 256, SM_TOT>>>(p_mean, p_xh, W_l0, W_r0,      128, 128, b_l0, p_h,  NN);
    k_gemm_h<<<GB, 256, SM_TOT>>>(p_xh,   p_h,  W_c,  W_c + 128, 256, 256, b_c,  p_x1, NN);

    // layer 1
    k_aggregate<<<(NN + 7) / 8, 256>>>(p_x1, p_mean);
    k_gemm_h<<<GB, 256, SM_TOT>>>(p_mean, p_x1, W_l1, W_r1,      128, 128, b_l1, p_h,  NN);
    k_gemm_h<<<GB, 256, SM_TOT>>>(p_x1,   p_h,  W_c,  W_c + 128, 256, 256, b_c,  p_x2, NN);

    // edge head via linearity: out = P[src] + Q[dst] + b_o
    k_pq<<<(NN + 255) / 256, 256>>>(p_x2, W_o);
    k_edge<<<(4 * NE + 255) / 256, 256>>>(ei, b_o, out);
}

// round 9
// speedup vs baseline: 2.6444x; 1.1386x over previous
#include <cuda_runtime.h>
#include <cuda_fp16.h>
#include <cstdint>

#define NN 100000
#define NE 1000000
#define D  128

// ---------------- scratch (device globals; no allocations allowed) ----------
__device__ int    g_cnt[NN + 1];
__device__ int    g_off[NN + 2];
__device__ int    g_pos[NN];
__device__ int    g_srcs[NE];
__device__ int    g_part[128];
__device__ __half g_xh   [(size_t)NN * D];   // fp16 copy of input x
__device__ __half g_meanh[(size_t)NN * D];
__device__ __half g_x1h  [(size_t)NN * D];
__device__ __half g_x2h  [(size_t)NN * D];
__device__ float  g_P    [(size_t)NN * 16];
__device__ float  g_Q    [(size_t)NN * 16];
// fp16 weights (pre-converted once per call)
__device__ __half g_wl0h[128 * 128];
__device__ __half g_wr0h[128 * 128];
__device__ __half g_wl1h[128 * 128];
__device__ __half g_wr1h[128 * 128];
__device__ __half g_wch [128 * 256];

// ---------------- helpers ----------------------------------------------------
__device__ __forceinline__ uint32_t smem_u32(const void* p) {
    uint32_t a;
    asm("{ .reg .u64 t; cvta.to.shared.u64 t, %1; cvt.u32.u64 %0, t; }"
        : "=r"(a) : "l"(p));
    return a;
}
__device__ __forceinline__ uint32_t pkh(float lo, float hi) {
    uint32_t d;  // bits[15:0]=f16(lo), bits[31:16]=f16(hi)
    asm("cvt.rn.f16x2.f32 %0, %1, %2;" : "=r"(d) : "f"(hi), "f"(lo));
    return d;
}
__device__ __forceinline__ void ldsm4(uint32_t* r, uint32_t addr) {
    asm volatile("ldmatrix.sync.aligned.m8n8.x4.shared.b16 {%0,%1,%2,%3}, [%4];"
                 : "=r"(r[0]), "=r"(r[1]), "=r"(r[2]), "=r"(r[3]) : "r"(addr));
}
__device__ __forceinline__ void mma_f16(float* d, const uint32_t* a,
                                        const uint32_t* b) {
    asm volatile(
        "mma.sync.aligned.m16n8k16.row.col.f32.f16.f16.f32 "
        "{%0,%1,%2,%3}, {%4,%5,%6,%7}, {%8,%9}, {%0,%1,%2,%3};"
        : "+f"(d[0]), "+f"(d[1]), "+f"(d[2]), "+f"(d[3])
        : "r"(a[0]), "r"(a[1]), "r"(a[2]), "r"(a[3]), "r"(b[0]), "r"(b[1]));
}

// ---------------- fp32 -> fp16 conversions -----------------------------------
__global__ void k_tohalf(const float* __restrict__ x) {
    int i = blockIdx.x * blockDim.x + threadIdx.x;   // over NN*32 float4s
    if (i < NN * 32) {
        float4 v = reinterpret_cast<const float4*>(x)[i];
        uint2 h;
        h.x = pkh(v.x, v.y);
        h.y = pkh(v.z, v.w);
        reinterpret_cast<uint2*>(g_xh)[i] = h;
    }
}

__global__ void k_convw(const float* __restrict__ wl0, const float* __restrict__ wr0,
                        const float* __restrict__ wl1, const float* __restrict__ wr1,
                        const float* __restrict__ wc) {
    int i = blockIdx.x * blockDim.x + threadIdx.x;   // 98304 total
    if (i < 16384)       g_wl0h[i]         = __float2half(wl0[i]);
    else if (i < 32768)  g_wr0h[i - 16384] = __float2half(wr0[i - 16384]);
    else if (i < 49152)  g_wl1h[i - 32768] = __float2half(wl1[i - 32768]);
    else if (i < 65536)  g_wr1h[i - 49152] = __float2half(wr1[i - 49152]);
    else if (i < 98304)  g_wch[i - 65536]  = __float2half(wc[i - 65536]);
}

// ---------------- CSR build (edge_index is int32: JAX x64 disabled) ----------
__global__ void k_count(const int* __restrict__ ei) {
    int e = blockIdx.x * blockDim.x + threadIdx.x;
    if (e < NE) {
        unsigned d = (unsigned)ei[NE + e];
        if (d < NN) atomicAdd(&g_cnt[d], 1);
    }
}

__global__ void k_scan_block() {   // per-block exclusive scan of g_cnt -> g_off
    __shared__ int sh[1024];
    int i = blockIdx.x * 1024 + threadIdx.x;
    int v = (i < NN) ? g_cnt[i] : 0;
    sh[threadIdx.x] = v;
    __syncthreads();
    for (int off = 1; off < 1024; off <<= 1) {
        int t = (threadIdx.x >= off) ? sh[threadIdx.x - off] : 0;
        __syncthreads();
        sh[threadIdx.x] += t;
        __syncthreads();
    }
    if (i < NN) g_off[i] = sh[threadIdx.x] - v;   // exclusive
    if (threadIdx.x == 1023) g_part[blockIdx.x] = sh[1023];
}

__global__ void k_scan_add() {   // parallel scan over block partials
    __shared__ int sp[128];
    int b = blockIdx.x;
    int nb = gridDim.x;
    if (threadIdx.x < 128)
        sp[threadIdx.x] = (threadIdx.x < nb) ? g_part[threadIdx.x] : 0;
    __syncthreads();
    for (int off = 1; off < 128; off <<= 1) {
        int t = 0;
        if (threadIdx.x < 128 && threadIdx.x >= off) t = sp[threadIdx.x - off];
        __syncthreads();
        if (threadIdx.x < 128) sp[threadIdx.x] += t;
        __syncthreads();
    }
    int s_base = (b == 0) ? 0 : sp[b - 1];
    int i = b * 1024 + threadIdx.x;
    if (i < NN) {
        int o = g_off[i] + s_base;
        g_off[i] = o;
        g_pos[i] = o;
    }
    if (i == 0) g_off[NN] = NE;
}

__global__ void k_fill(const int* __restrict__ ei) {
    int e = blockIdx.x * blockDim.x + threadIdx.x;
    if (e < NE) {
        unsigned d = (unsigned)ei[NE + e];
        if (d < NN) {
            int p = atomicAdd(&g_pos[d], 1);
            if (p >= 0 && p < NE) g_srcs[p] = ei[e];
        }
    }
}

// ---------------- mean aggregation (fp16 rows): one warp per node ------------
__global__ void k_aggregate(const __half* __restrict__ xin,
                            __half* __restrict__ mout) {
    int n = blockIdx.x * (blockDim.x >> 5) + (threadIdx.x >> 5);
    if (n >= NN) return;
    int lane = threadIdx.x & 31;
    int beg = g_off[n], end = g_off[n + 1];
    float ax = 0.f, ay = 0.f, az = 0.f, aw = 0.f;
    for (int t = beg; t < end; t++) {
        unsigned s = (unsigned)g_srcs[t];
        if (s >= NN) continue;
        uint2 v = *reinterpret_cast<const uint2*>(xin + (size_t)s * D + lane * 4);
        __half2 h0 = *reinterpret_cast<__half2*>(&v.x);
        __half2 h1 = *reinterpret_cast<__half2*>(&v.y);
        float2 f0 = __half22float2(h0), f1 = __half22float2(h1);
        ax += f0.x; ay += f0.y; az += f1.x; aw += f1.y;
    }
    int c = end - beg;
    float inv = 1.0f / (float)(c > 0 ? c : 1);
    uint2 o;
    o.x = pkh(ax * inv, ay * inv);
    o.y = pkh(az * inv, aw * inv);
    *reinterpret_cast<uint2*>(mout + (size_t)n * D + lane * 4) = o;
}

// ---------------- fused SAGE layer: x' = relu([x|h]Wc^T + bc),
//                  h = relu([mean|x]W^T + bl), h lives only in SMEM ----------
// 256 threads (8 warps, warp tile 32m x 64n), BM=BN=128.
// SMEM: sX (x tile), sMH (mean tile, overwritten by h), sB (weight tile).
#define SROW   272
#define SX_OFF 0
#define SMH_OFF 34816
#define SB_OFF 69632
#define SM_TOT 104448

struct MmaCtx {
    uint32_t smb, aoff, boff;
    int m0, n0;
};

__device__ __forceinline__ void mma_tiles(const MmaCtx& c, uint32_t a_off_base,
                                          float acc[2][8][4]) {
    #pragma unroll
    for (int ks = 0; ks < 8; ks++) {
        uint32_t a0[4], a1[4], bf[4][4];
        ldsm4(a0, c.smb + a_off_base + (uint32_t)(c.m0 * SROW) + ks * 32 + c.aoff);
        ldsm4(a1, c.smb + a_off_base + (uint32_t)((c.m0 + 16) * SROW) + ks * 32 + c.aoff);
        #pragma unroll
        for (int nb = 0; nb < 4; nb++)
            ldsm4(bf[nb], c.smb + SB_OFF + (uint32_t)((c.n0 + nb * 16) * SROW)
                          + ks * 32 + c.boff);
        #pragma unroll
        for (int nb = 0; nb < 4; nb++) {
            mma_f16(acc[0][nb * 2 + 0], a0, &bf[nb][0]);
            mma_f16(acc[0][nb * 2 + 1], a0, &bf[nb][2]);
            mma_f16(acc[1][nb * 2 + 0], a1, &bf[nb][0]);
            mma_f16(acc[1][nb * 2 + 1], a1, &bf[nb][2]);
        }
    }
}

__device__ __forceinline__ void load_b(char* sm, const __half* __restrict__ w,
                                       int stride, int tid) {
    #pragma unroll
    for (int i = 0; i < 8; i++) {
        int idx = tid + i * 256;          // 0..2047
        int r = idx >> 4, cc = idx & 15;
        uint4 v = *reinterpret_cast<const uint4*>(w + (size_t)r * stride + cc * 8);
        *reinterpret_cast<uint4*>(sm + SB_OFF + r * SROW + cc * 16) = v;
    }
}

__global__ void __launch_bounds__(256, 2) k_layer(
    const __half* __restrict__ X, const __half* __restrict__ MEAN,
    const __half* __restrict__ Wl, const __half* __restrict__ Wr,
    const __half* __restrict__ Wc,
    const float* __restrict__ bl, const float* __restrict__ bc,
    __half* __restrict__ OUT, int nrows)
{
    extern __shared__ __align__(16) char sm[];
    uint32_t smb = smem_u32(sm);
    int tid = threadIdx.x, lane = tid & 31, wid = tid >> 5;
    int row0 = blockIdx.x * 128;

    MmaCtx c;
    c.smb = smb;
    c.m0 = (wid >> 1) * 32;
    c.n0 = (wid & 1) * 64;
    {
        int t = lane >> 3, rr = lane & 7;
        c.aoff = (uint32_t)((lane & 15) * SROW + (lane >> 4) * 16);
        c.boff = (uint32_t)((((t >> 1) * 8 + rr) * SROW) + (t & 1) * 16);
    }

    // load x and mean tiles (fp16 straight copies)
    #pragma unroll
    for (int i = 0; i < 8; i++) {
        int idx = tid + i * 256;
        int r = idx >> 4, cc = idx & 15;
        int gr = row0 + r;
        uint4 vx = make_uint4(0u, 0u, 0u, 0u), vm = vx;
        if (gr < nrows) {
            vx = *reinterpret_cast<const uint4*>(X + (size_t)gr * D + cc * 8);
            vm = *reinterpret_cast<const uint4*>(MEAN + (size_t)gr * D + cc * 8);
        }
        *reinterpret_cast<uint4*>(sm + SX_OFF + r * SROW + cc * 16) = vx;
        *reinterpret_cast<uint4*>(sm + SMH_OFF + r * SROW + cc * 16) = vm;
    }
    load_b(sm, Wl, 128, tid);
    __syncthreads();

    float acc[2][8][4];
    #pragma unroll
    for (int i = 0; i < 2; i++)
        #pragma unroll
        for (int j = 0; j < 8; j++)
            #pragma unroll
            for (int q = 0; q < 4; q++) acc[i][j][q] = 0.f;

    // GEMM1 phase a: mean x Wl
    mma_tiles(c, SMH_OFF, acc);
    __syncthreads();
    load_b(sm, Wr, 128, tid);
    __syncthreads();
    // GEMM1 phase b: x x Wr
    mma_tiles(c, SX_OFF, acc);

    // epilogue 1: h = relu(acc + bl) -> SMEM (overwrites mean tile)
    #pragma unroll
    for (int mi = 0; mi < 2; mi++) {
        int r0 = c.m0 + mi * 16 + (lane >> 2);
        #pragma unroll
        for (int f = 0; f < 8; f++) {
            int col = c.n0 + f * 8 + (lane & 3) * 2;
            float2 bv = *reinterpret_cast<const float2*>(bl + col);
            uint32_t h0 = pkh(fmaxf(acc[mi][f][0] + bv.x, 0.f),
                              fmaxf(acc[mi][f][1] + bv.y, 0.f));
            uint32_t h1 = pkh(fmaxf(acc[mi][f][2] + bv.x, 0.f),
                              fmaxf(acc[mi][f][3] + bv.y, 0.f));
            *reinterpret_cast<uint32_t*>(sm + SMH_OFF + r0 * SROW + col * 2) = h0;
            *reinterpret_cast<uint32_t*>(sm + SMH_OFF + (r0 + 8) * SROW + col * 2) = h1;
        }
    }
    __syncthreads();
    load_b(sm, Wc, 256, tid);          // Wc k-cols [0,128) -> multiplies x
    __syncthreads();

    #pragma unroll
    for (int i = 0; i < 2; i++)
        #pragma unroll
        for (int j = 0; j < 8; j++)
            #pragma unroll
            for (int q = 0; q < 4; q++) acc[i][j][q] = 0.f;

    // GEMM2 phase a: x x Wc1
    mma_tiles(c, SX_OFF, acc);
    __syncthreads();
    load_b(sm, Wc + 128, 256, tid);    // Wc k-cols [128,256) -> multiplies h
    __syncthreads();
    // GEMM2 phase b: h x Wc2
    mma_tiles(c, SMH_OFF, acc);

    // epilogue 2: x' = relu(acc + bc) -> global fp16
    #pragma unroll
    for (int mi = 0; mi < 2; mi++) {
        int gr0 = row0 + c.m0 + mi * 16 + (lane >> 2);
        #pragma unroll
        for (int f = 0; f < 8; f++) {
            int col = c.n0 + f * 8 + (lane & 3) * 2;
            float2 bv = *reinterpret_cast<const float2*>(bc + col);
            if (gr0 < nrows) {
                uint32_t h = pkh(fmaxf(acc[mi][f][0] + bv.x, 0.f),
                                 fmaxf(acc[mi][f][1] + bv.y, 0.f));
                *reinterpret_cast<uint32_t*>(OUT + (size_t)gr0 * D + col) = h;
            }
            if (gr0 + 8 < nrows) {
                uint32_t h = pkh(fmaxf(acc[mi][f][2] + bv.x, 0.f),
                                 fmaxf(acc[mi][f][3] + bv.y, 0.f));
                *reinterpret_cast<uint32_t*>(OUT + (size_t)(gr0 + 8) * D + col) = h;
            }
        }
    }
}

// ---------------- P/Q: N x 16 projections of x2 (fp16) with W_o halves ------
__global__ void __launch_bounds__(256) k_pq(const __half* __restrict__ x,
                                            const float* __restrict__ Wo) {
    __shared__ __align__(16) float sw[16 * 256];
    for (int i = threadIdx.x; i < 4096; i += 256) sw[i] = Wo[i];
    __syncthreads();
    int n = blockIdx.x * 256 + threadIdx.x;
    if (n >= NN) return;
    const uint4* xr = reinterpret_cast<const uint4*>(x + (size_t)n * D);
    float accP[16], accQ[16];
    #pragma unroll
    for (int j = 0; j < 16; j++) { accP[j] = 0.f; accQ[j] = 0.f; }
    #pragma unroll 2
    for (int k8 = 0; k8 < 16; k8++) {
        uint4 hv = xr[k8];
        float xv[8];
        {
            float2 f0 = __half22float2(*reinterpret_cast<__half2*>(&hv.x));
            float2 f1 = __half22float2(*reinterpret_cast<__half2*>(&hv.y));
            float2 f2 = __half22float2(*reinterpret_cast<__half2*>(&hv.z));
            float2 f3 = __half22float2(*reinterpret_cast<__half2*>(&hv.w));
            xv[0] = f0.x; xv[1] = f0.y; xv[2] = f1.x; xv[3] = f1.y;
            xv[4] = f2.x; xv[5] = f2.y; xv[6] = f3.x; xv[7] = f3.y;
        }
        #pragma unroll
        for (int j = 0; j < 16; j++) {
            const float* wa = &sw[j * 256 + k8 * 8];
            const float* wb = &sw[j * 256 + 128 + k8 * 8];
            #pragma unroll
            for (int q = 0; q < 8; q++) {
                accP[j] += xv[q] * wa[q];
                accQ[j] += xv[q] * wb[q];
            }
        }
    }
    #pragma unroll
    for (int j = 0; j < 16; j++) {
        g_P[(size_t)n * 16 + j] = accP[j];
        g_Q[(size_t)n * 16 + j] = accQ[j];
    }
}

// ---------------- edge head: out[e] = P[src] + Q[dst] + b_o ------------------
__global__ void k_edge(const int* __restrict__ ei,
                       const float* __restrict__ bo, float* __restrict__ out) {
    int t = blockIdx.x * blockDim.x + threadIdx.x;
    if (t >= NE * 4) return;
    int e = t >> 2, q = t & 3;
    unsigned s = (unsigned)ei[e];
    unsigned d = (unsigned)ei[NE + e];
    float4 p  = (s < NN) ? reinterpret_cast<const float4*>(g_P)[(size_t)s * 4 + q]
                         : make_float4(0.f, 0.f, 0.f, 0.f);
    float4 qv = (d < NN) ? reinterpret_cast<const float4*>(g_Q)[(size_t)d * 4 + q]
                         : make_float4(0.f, 0.f, 0.f, 0.f);
    float4 b = reinterpret_cast<const float4*>(bo)[q];
    float4 o;
    o.x = p.x + qv.x + b.x; o.y = p.y + qv.y + b.y;
    o.z = p.z + qv.z + b.z; o.w = p.w + qv.w + b.w;
    reinterpret_cast<float4*>(out)[(size_t)e * 4 + q] = o;
}

// ---------------- launch -----------------------------------------------------
extern "C" void kernel_launch(void* const* d_in, const int* in_sizes, int n_in,
                              void* d_out, int out_size) {
    const float* x    = (const float*)d_in[0];
    const int*   ei   = (const int*)d_in[1];     // int32: JAX x64 is disabled
    const float* W_l0 = (const float*)d_in[2];
    const float* b_l0 = (const float*)d_in[3];
    const float* W_r0 = (const float*)d_in[4];
    const float* W_l1 = (const float*)d_in[5];
    const float* b_l1 = (const float*)d_in[6];
    const float* W_r1 = (const float*)d_in[7];
    const float* W_c  = (const float*)d_in[8];
    const float* b_c  = (const float*)d_in[9];
    const float* W_o  = (const float*)d_in[10];
    const float* b_o  = (const float*)d_in[11];
    float*       out  = (float*)d_out;

    __half *p_xh, *p_mean, *p_x1, *p_x2;
    __half *p_wl0, *p_wr0, *p_wl1, *p_wr1, *p_wc;
    int* p_cnt;
    cudaGetSymbolAddress((void**)&p_xh,   g_xh);
    cudaGetSymbolAddress((void**)&p_mean, g_meanh);
    cudaGetSymbolAddress((void**)&p_x1,   g_x1h);
    cudaGetSymbolAddress((void**)&p_x2,   g_x2h);
    cudaGetSymbolAddress((void**)&p_wl0,  g_wl0h);
    cudaGetSymbolAddress((void**)&p_wr0,  g_wr0h);
    cudaGetSymbolAddress((void**)&p_wl1,  g_wl1h);
    cudaGetSymbolAddress((void**)&p_wr1,  g_wr1h);
    cudaGetSymbolAddress((void**)&p_wc,   g_wch);
    cudaGetSymbolAddress((void**)&p_cnt,  g_cnt);

    cudaFuncSetAttribute(k_layer,
                         cudaFuncAttributeMaxDynamicSharedMemorySize, SM_TOT);

    const int SCAN_NB = (NN + 1023) / 1024;
    const int GB = (NN + 127) / 128;

    // conversions + CSR build
    k_tohalf<<<(NN * 32 + 255) / 256, 256>>>(x);
    k_convw<<<(98304 + 255) / 256, 256>>>(W_l0, W_r0, W_l1, W_r1, W_c);
    cudaMemsetAsync(p_cnt, 0, (NN + 1) * sizeof(int));
    k_count<<<(NE + 255) / 256, 256>>>(ei);
    k_scan_block<<<SCAN_NB, 1024>>>();
    k_scan_add<<<SCAN_NB, 1024>>>();
    k_fill<<<(NE + 255) / 256, 256>>>(ei);

    // layer 0 (fused dual GEMM, h SMEM-only)
    k_aggregate<<<(NN + 7) / 8, 256>>>(p_xh, p_mean);
    k_layer<<<GB, 256, SM_TOT>>>(p_xh, p_mean, p_wl0, p_wr0, p_wc,
                                 b_l0, b_c, p_x1, NN);

    // layer 1
    k_aggregate<<<(NN + 7) / 8, 256>>>(p_x1, p_mean);
    k_layer<<<GB, 256, SM_TOT>>>(p_x1, p_mean, p_wl1, p_wr1, p_wc,
                                 b_l1, b_c, p_x2, NN);

    // edge head via linearity: out = P[src] + Q[dst] + b_o
    k_pq<<<(NN + 255) / 256, 256>>>(p_x2, W_o);
    k_edge<<<(4 * NE + 255) / 256, 256>>>(ei, b_o, out);
}

// round 11
// speedup vs baseline: 3.1145x; 1.1778x over previous
#include <cuda_runtime.h>
#include <cuda_fp16.h>
#include <cstdint>

#define NN 100000
#define NE 1000000
#define D  128

// ---------------- scratch (device globals; no allocations allowed) ----------
__device__ int    g_cnt[NN + 1];
__device__ int    g_off[NN + 2];
__device__ int    g_pos[NN];
__device__ int    g_srcs[NE];
__device__ int    g_part[128];
__device__ __half g_xh   [(size_t)NN * D];   // fp16 copy of input x
__device__ __half g_meanh[(size_t)NN * D];
__device__ __half g_x1h  [(size_t)NN * D];
__device__ __half g_x2h  [(size_t)NN * D];
__device__ float  g_P    [(size_t)NN * 16];  // P + b_o (bias folded)
__device__ float  g_Q    [(size_t)NN * 16];
// fp16 weights (pre-converted once per call)
__device__ __half g_wl0h[128 * 128];
__device__ __half g_wr0h[128 * 128];
__device__ __half g_wl1h[128 * 128];
__device__ __half g_wr1h[128 * 128];
__device__ __half g_wch [128 * 256];

// ---------------- helpers ----------------------------------------------------
__device__ __forceinline__ uint32_t smem_u32(const void* p) {
    uint32_t a;
    asm("{ .reg .u64 t; cvta.to.shared.u64 t, %1; cvt.u32.u64 %0, t; }"
        : "=r"(a) : "l"(p));
    return a;
}
__device__ __forceinline__ uint32_t pkh(float lo, float hi) {
    uint32_t d;  // bits[15:0]=f16(lo), bits[31:16]=f16(hi)
    asm("cvt.rn.f16x2.f32 %0, %1, %2;" : "=r"(d) : "f"(hi), "f"(lo));
    return d;
}
__device__ __forceinline__ void ldsm4(uint32_t* r, uint32_t addr) {
    asm volatile("ldmatrix.sync.aligned.m8n8.x4.shared.b16 {%0,%1,%2,%3}, [%4];"
                 : "=r"(r[0]), "=r"(r[1]), "=r"(r[2]), "=r"(r[3]) : "r"(addr));
}
__device__ __forceinline__ void mma_f16(float* d, const uint32_t* a,
                                        const uint32_t* b) {
    asm volatile(
        "mma.sync.aligned.m16n8k16.row.col.f32.f16.f16.f32 "
        "{%0,%1,%2,%3}, {%4,%5,%6,%7}, {%8,%9}, {%0,%1,%2,%3};"
        : "+f"(d[0]), "+f"(d[1]), "+f"(d[2]), "+f"(d[3])
        : "r"(a[0]), "r"(a[1]), "r"(a[2]), "r"(a[3]), "r"(b[0]), "r"(b[1]));
}

// ---------------- fp32 -> fp16 conversions -----------------------------------
__global__ void k_tohalf(const float* __restrict__ x) {
    int i = blockIdx.x * blockDim.x + threadIdx.x;   // over NN*32 float4s
    if (i < NN * 32) {
        float4 v = reinterpret_cast<const float4*>(x)[i];
        uint2 h;
        h.x = pkh(v.x, v.y);
        h.y = pkh(v.z, v.w);
        reinterpret_cast<uint2*>(g_xh)[i] = h;
    }
}

__global__ void k_convw(const float* __restrict__ wl0, const float* __restrict__ wr0,
                        const float* __restrict__ wl1, const float* __restrict__ wr1,
                        const float* __restrict__ wc) {
    int i = blockIdx.x * blockDim.x + threadIdx.x;   // 98304 total
    if (i < 16384)       g_wl0h[i]         = __float2half(wl0[i]);
    else if (i < 32768)  g_wr0h[i - 16384] = __float2half(wr0[i - 16384]);
    else if (i < 49152)  g_wl1h[i - 32768] = __float2half(wl1[i - 32768]);
    else if (i < 65536)  g_wr1h[i - 49152] = __float2half(wr1[i - 49152]);
    else if (i < 98304)  g_wch[i - 65536]  = __float2half(wc[i - 65536]);
}

// ---------------- CSR build (edge_index is int32: JAX x64 disabled) ----------
__global__ void k_count(const int* __restrict__ ei) {
    int e = blockIdx.x * blockDim.x + threadIdx.x;
    if (e < NE) {
        unsigned d = (unsigned)ei[NE + e];
        if (d < NN) atomicAdd(&g_cnt[d], 1);
    }
}

__global__ void k_scan_block() {   // per-block exclusive scan of g_cnt -> g_off
    __shared__ int sh[1024];
    int i = blockIdx.x * 1024 + threadIdx.x;
    int v = (i < NN) ? g_cnt[i] : 0;
    sh[threadIdx.x] = v;
    __syncthreads();
    for (int off = 1; off < 1024; off <<= 1) {
        int t = (threadIdx.x >= off) ? sh[threadIdx.x - off] : 0;
        __syncthreads();
        sh[threadIdx.x] += t;
        __syncthreads();
    }
    if (i < NN) g_off[i] = sh[threadIdx.x] - v;   // exclusive
    if (threadIdx.x == 1023) g_part[blockIdx.x] = sh[1023];
}

__global__ void k_scan_add() {   // parallel scan over block partials
    __shared__ int sp[128];
    int b = blockIdx.x;
    int nb = gridDim.x;
    if (threadIdx.x < 128)
        sp[threadIdx.x] = (threadIdx.x < nb) ? g_part[threadIdx.x] : 0;
    __syncthreads();
    for (int off = 1; off < 128; off <<= 1) {
        int t = 0;
        if (threadIdx.x < 128 && threadIdx.x >= off) t = sp[threadIdx.x - off];
        __syncthreads();
        if (threadIdx.x < 128) sp[threadIdx.x] += t;
        __syncthreads();
    }
    int s_base = (b == 0) ? 0 : sp[b - 1];
    int i = b * 1024 + threadIdx.x;
    if (i < NN) {
        int o = g_off[i] + s_base;
        g_off[i] = o;
        g_pos[i] = o;
    }
    if (i == 0) g_off[NN] = NE;
}

__global__ void k_fill(const int* __restrict__ ei) {
    int e = blockIdx.x * blockDim.x + threadIdx.x;
    if (e < NE) {
        unsigned d = (unsigned)ei[NE + e];
        if (d < NN) {
            int p = atomicAdd(&g_pos[d], 1);
            if (p >= 0 && p < NE) g_srcs[p] = ei[e];
        }
    }
}

// ---------------- mean aggregation (fp16 rows): one warp per node ------------
__global__ void k_aggregate(const __half* __restrict__ xin,
                            __half* __restrict__ mout) {
    int n = blockIdx.x * (blockDim.x >> 5) + (threadIdx.x >> 5);
    if (n >= NN) return;
    int lane = threadIdx.x & 31;
    int beg = g_off[n], end = g_off[n + 1];
    float ax = 0.f, ay = 0.f, az = 0.f, aw = 0.f;
    #pragma unroll 4
    for (int t = beg; t < end; t++) {
        unsigned s = (unsigned)g_srcs[t];
        if (s >= NN) continue;
        uint2 v = *reinterpret_cast<const uint2*>(xin + (size_t)s * D + lane * 4);
        __half2 h0 = *reinterpret_cast<__half2*>(&v.x);
        __half2 h1 = *reinterpret_cast<__half2*>(&v.y);
        float2 f0 = __half22float2(h0), f1 = __half22float2(h1);
        ax += f0.x; ay += f0.y; az += f1.x; aw += f1.y;
    }
    int c = end - beg;
    float inv = 1.0f / (float)(c > 0 ? c : 1);
    uint2 o;
    o.x = pkh(ax * inv, ay * inv);
    o.y = pkh(az * inv, aw * inv);
    *reinterpret_cast<uint2*>(mout + (size_t)n * D + lane * 4) = o;
}

// ---------------- fused SAGE layer: x' = relu([x|h]Wc^T + bc),
//                  h = relu([mean|x]W^T + bl), h lives only in SMEM ----------
// 256 threads (8 warps, warp tile 32m x 64n), BM=BN=128.
#define SROW   272
#define SX_OFF 0
#define SMH_OFF 34816
#define SB_OFF 69632
#define SM_TOT 104448

struct MmaCtx {
    uint32_t smb, aoff, boff;
    int m0, n0;
};

__device__ __forceinline__ void mma_tiles(const MmaCtx& c, uint32_t a_off_base,
                                          float acc[2][8][4]) {
    #pragma unroll
    for (int ks = 0; ks < 8; ks++) {
        uint32_t a0[4], a1[4], bf[4][4];
        ldsm4(a0, c.smb + a_off_base + (uint32_t)(c.m0 * SROW) + ks * 32 + c.aoff);
        ldsm4(a1, c.smb + a_off_base + (uint32_t)((c.m0 + 16) * SROW) + ks * 32 + c.aoff);
        #pragma unroll
        for (int nb = 0; nb < 4; nb++)
            ldsm4(bf[nb], c.smb + SB_OFF + (uint32_t)((c.n0 + nb * 16) * SROW)
                          + ks * 32 + c.boff);
        #pragma unroll
        for (int nb = 0; nb < 4; nb++) {
            mma_f16(acc[0][nb * 2 + 0], a0, &bf[nb][0]);
            mma_f16(acc[0][nb * 2 + 1], a0, &bf[nb][2]);
            mma_f16(acc[1][nb * 2 + 0], a1, &bf[nb][0]);
            mma_f16(acc[1][nb * 2 + 1], a1, &bf[nb][2]);
        }
    }
}

__device__ __forceinline__ void load_b(char* sm, const __half* __restrict__ w,
                                       int stride, int tid) {
    #pragma unroll
    for (int i = 0; i < 8; i++) {
        int idx = tid + i * 256;          // 0..2047
        int r = idx >> 4, cc = idx & 15;
        uint4 v = *reinterpret_cast<const uint4*>(w + (size_t)r * stride + cc * 8);
        *reinterpret_cast<uint4*>(sm + SB_OFF + r * SROW + cc * 16) = v;
    }
}

__global__ void __launch_bounds__(256, 2) k_layer(
    const __half* __restrict__ X, const __half* __restrict__ MEAN,
    const __half* __restrict__ Wl, const __half* __restrict__ Wr,
    const __half* __restrict__ Wc,
    const float* __restrict__ bl, const float* __restrict__ bc,
    __half* __restrict__ OUT, int nrows)
{
    extern __shared__ __align__(16) char sm[];
    uint32_t smb = smem_u32(sm);
    int tid = threadIdx.x, lane = tid & 31, wid = tid >> 5;
    int row0 = blockIdx.x * 128;

    MmaCtx c;
    c.smb = smb;
    c.m0 = (wid >> 1) * 32;
    c.n0 = (wid & 1) * 64;
    {
        int t = lane >> 3, rr = lane & 7;
        c.aoff = (uint32_t)((lane & 15) * SROW + (lane >> 4) * 16);
        c.boff = (uint32_t)((((t >> 1) * 8 + rr) * SROW) + (t & 1) * 16);
    }

    // load x and mean tiles (fp16 straight copies)
    #pragma unroll
    for (int i = 0; i < 8; i++) {
        int idx = tid + i * 256;
        int r = idx >> 4, cc = idx & 15;
        int gr = row0 + r;
        uint4 vx = make_uint4(0u, 0u, 0u, 0u), vm = vx;
        if (gr < nrows) {
            vx = *reinterpret_cast<const uint4*>(X + (size_t)gr * D + cc * 8);
            vm = *reinterpret_cast<const uint4*>(MEAN + (size_t)gr * D + cc * 8);
        }
        *reinterpret_cast<uint4*>(sm + SX_OFF + r * SROW + cc * 16) = vx;
        *reinterpret_cast<uint4*>(sm + SMH_OFF + r * SROW + cc * 16) = vm;
    }
    load_b(sm, Wl, 128, tid);
    __syncthreads();

    float acc[2][8][4];
    #pragma unroll
    for (int i = 0; i < 2; i++)
        #pragma unroll
        for (int j = 0; j < 8; j++)
            #pragma unroll
            for (int q = 0; q < 4; q++) acc[i][j][q] = 0.f;

    // GEMM1 phase a: mean x Wl
    mma_tiles(c, SMH_OFF, acc);
    __syncthreads();
    load_b(sm, Wr, 128, tid);
    __syncthreads();
    // GEMM1 phase b: x x Wr
    mma_tiles(c, SX_OFF, acc);

    // epilogue 1: h = relu(acc + bl) -> SMEM (overwrites mean tile)
    #pragma unroll
    for (int mi = 0; mi < 2; mi++) {
        int r0 = c.m0 + mi * 16 + (lane >> 2);
        #pragma unroll
        for (int f = 0; f < 8; f++) {
            int col = c.n0 + f * 8 + (lane & 3) * 2;
            float2 bv = *reinterpret_cast<const float2*>(bl + col);
            uint32_t h0 = pkh(fmaxf(acc[mi][f][0] + bv.x, 0.f),
                              fmaxf(acc[mi][f][1] + bv.y, 0.f));
            uint32_t h1 = pkh(fmaxf(acc[mi][f][2] + bv.x, 0.f),
                              fmaxf(acc[mi][f][3] + bv.y, 0.f));
            *reinterpret_cast<uint32_t*>(sm + SMH_OFF + r0 * SROW + col * 2) = h0;
            *reinterpret_cast<uint32_t*>(sm + SMH_OFF + (r0 + 8) * SROW + col * 2) = h1;
        }
    }
    __syncthreads();
    load_b(sm, Wc, 256, tid);          // Wc k-cols [0,128) -> multiplies x
    __syncthreads();

    #pragma unroll
    for (int i = 0; i < 2; i++)
        #pragma unroll
        for (int j = 0; j < 8; j++)
            #pragma unroll
            for (int q = 0; q < 4; q++) acc[i][j][q] = 0.f;

    // GEMM2 phase a: x x Wc1
    mma_tiles(c, SX_OFF, acc);
    __syncthreads();
    load_b(sm, Wc + 128, 256, tid);    // Wc k-cols [128,256) -> multiplies h
    __syncthreads();
    // GEMM2 phase b: h x Wc2
    mma_tiles(c, SMH_OFF, acc);

    // epilogue 2: x' = relu(acc + bc) -> global fp16
    #pragma unroll
    for (int mi = 0; mi < 2; mi++) {
        int gr0 = row0 + c.m0 + mi * 16 + (lane >> 2);
        #pragma unroll
        for (int f = 0; f < 8; f++) {
            int col = c.n0 + f * 8 + (lane & 3) * 2;
            float2 bv = *reinterpret_cast<const float2*>(bc + col);
            if (gr0 < nrows) {
                uint32_t h = pkh(fmaxf(acc[mi][f][0] + bv.x, 0.f),
                                 fmaxf(acc[mi][f][1] + bv.y, 0.f));
                *reinterpret_cast<uint32_t*>(OUT + (size_t)gr0 * D + col) = h;
            }
            if (gr0 + 8 < nrows) {
                uint32_t h = pkh(fmaxf(acc[mi][f][2] + bv.x, 0.f),
                                 fmaxf(acc[mi][f][3] + bv.y, 0.f));
                *reinterpret_cast<uint32_t*>(OUT + (size_t)(gr0 + 8) * D + col) = h;
            }
        }
    }
}

// ---------------- P/Q via HMMA: [NN,128] x [128,32] --------------------------
// B tile rows 0..15 = Wo[:, 0:128] (P), rows 16..31 = Wo[:, 128:256] (Q).
// P gets b_o folded in. 256 threads, 8 warps, each warp an m16 tile.
#define PQ_B_OFF 34816
__global__ void __launch_bounds__(256) k_pq(const __half* __restrict__ x,
                                            const float* __restrict__ Wo,
                                            const float* __restrict__ bo) {
    __shared__ __align__(16) char sm[34816 + 32 * SROW];
    uint32_t smb = smem_u32(sm);
    int tid = threadIdx.x, lane = tid & 31, wid = tid >> 5;
    int row0 = blockIdx.x * 128;

    // A tile: x rows (fp16 straight copies)
    #pragma unroll
    for (int i = 0; i < 8; i++) {
        int idx = tid + i * 256;
        int r = idx >> 4, cc = idx & 15;
        int gr = row0 + r;
        uint4 v = (gr < NN)
            ? *reinterpret_cast<const uint4*>(x + (size_t)gr * D + cc * 8)
            : make_uint4(0u, 0u, 0u, 0u);
        *reinterpret_cast<uint4*>(sm + r * SROW + cc * 16) = v;
    }
    // B tile: 32 rows x 128 halves from fp32 Wo
    #pragma unroll
    for (int i = 0; i < 4; i++) {
        int idx = tid + i * 256;          // 0..1023
        int r = idx >> 5, c4 = idx & 31;  // r: 0..31, c4: 0..31
        const float* src = (r < 16) ? (Wo + (size_t)r * 256 + c4 * 4)
                                    : (Wo + (size_t)(r - 16) * 256 + 128 + c4 * 4);
        float4 v = *reinterpret_cast<const float4*>(src);
        uint2 h;
        h.x = pkh(v.x, v.y);
        h.y = pkh(v.z, v.w);
        *reinterpret_cast<uint2*>(sm + PQ_B_OFF + r * SROW + c4 * 8) = h;
    }
    __syncthreads();

    int t = lane >> 3, rr = lane & 7;
    uint32_t aoff = (uint32_t)((lane & 15) * SROW + (lane >> 4) * 16);
    uint32_t boff = (uint32_t)((((t >> 1) * 8 + rr) * SROW) + (t & 1) * 16);
    int m0 = wid * 16;

    float acc[4][4];
    #pragma unroll
    for (int j = 0; j < 4; j++)
        #pragma unroll
        for (int q = 0; q < 4; q++) acc[j][q] = 0.f;

    #pragma unroll
    for (int ks = 0; ks < 8; ks++) {
        uint32_t a0[4], bf[2][4];
        ldsm4(a0, smb + (uint32_t)(m0 * SROW) + ks * 32 + aoff);
        ldsm4(bf[0], smb + PQ_B_OFF + ks * 32 + boff);
        ldsm4(bf[1], smb + PQ_B_OFF + (uint32_t)(16 * SROW) + ks * 32 + boff);
        mma_f16(acc[0], a0, &bf[0][0]);
        mma_f16(acc[1], a0, &bf[0][2]);
        mma_f16(acc[2], a0, &bf[1][0]);
        mma_f16(acc[3], a0, &bf[1][2]);
    }

    // epilogue: cols 0..15 -> P (+= b_o), cols 16..31 -> Q
    int gr0 = row0 + m0 + (lane >> 2);
    #pragma unroll
    for (int f = 0; f < 4; f++) {
        int col = f * 8 + (lane & 3) * 2;   // 0..30
        #pragma unroll
        for (int half = 0; half < 2; half++) {
            int gr = gr0 + half * 8;
            if (gr >= NN) continue;
            float2 v;
            v.x = acc[f][half * 2 + 0];
            v.y = acc[f][half * 2 + 1];
            if (col < 16) {
                float2 bv = *reinterpret_cast<const float2*>(bo + col);
                v.x += bv.x; v.y += bv.y;
                *reinterpret_cast<float2*>(g_P + (size_t)gr * 16 + col) = v;
            } else {
                *reinterpret_cast<float2*>(g_Q + (size_t)gr * 16 + (col - 16)) = v;
            }
        }
    }
}

// ---------------- edge head: out[e] = P'[src] + Q[dst] (bias pre-folded) -----
__global__ void k_edge(const int* __restrict__ ei, float* __restrict__ out) {
    int t = blockIdx.x * blockDim.x + threadIdx.x;
    if (t >= NE * 4) return;
    int e = t >> 2, q = t & 3;
    unsigned s = (unsigned)ei[e];
    unsigned d = (unsigned)ei[NE + e];
    float4 p  = (s < NN) ? reinterpret_cast<const float4*>(g_P)[(size_t)s * 4 + q]
                         : make_float4(0.f, 0.f, 0.f, 0.f);
    float4 qv = (d < NN) ? reinterpret_cast<const float4*>(g_Q)[(size_t)d * 4 + q]
                         : make_float4(0.f, 0.f, 0.f, 0.f);
    float4 o;
    o.x = p.x + qv.x; o.y = p.y + qv.y;
    o.z = p.z + qv.z; o.w = p.w + qv.w;
    __stcs(reinterpret_cast<float4*>(out) + (size_t)e * 4 + q, o);
}

// ---------------- launch -----------------------------------------------------
extern "C" void kernel_launch(void* const* d_in, const int* in_sizes, int n_in,
                              void* d_out, int out_size) {
    const float* x    = (const float*)d_in[0];
    const int*   ei   = (const int*)d_in[1];     // int32: JAX x64 is disabled
    const float* W_l0 = (const float*)d_in[2];
    const float* b_l0 = (const float*)d_in[3];
    const float* W_r0 = (const float*)d_in[4];
    const float* W_l1 = (const float*)d_in[5];
    const float* b_l1 = (const float*)d_in[6];
    const float* W_r1 = (const float*)d_in[7];
    const float* W_c  = (const float*)d_in[8];
    const float* b_c  = (const float*)d_in[9];
    const float* W_o  = (const float*)d_in[10];
    const float* b_o  = (const float*)d_in[11];
    float*       out  = (float*)d_out;

    __half *p_xh, *p_mean, *p_x1, *p_x2;
    __half *p_wl0, *p_wr0, *p_wl1, *p_wr1, *p_wc;
    int* p_cnt;
    cudaGetSymbolAddress((void**)&p_xh,   g_xh);
    cudaGetSymbolAddress((void**)&p_mean, g_meanh);
    cudaGetSymbolAddress((void**)&p_x1,   g_x1h);
    cudaGetSymbolAddress((void**)&p_x2,   g_x2h);
    cudaGetSymbolAddress((void**)&p_wl0,  g_wl0h);
    cudaGetSymbolAddress((void**)&p_wr0,  g_wr0h);
    cudaGetSymbolAddress((void**)&p_wl1,  g_wl1h);
    cudaGetSymbolAddress((void**)&p_wr1,  g_wr1h);
    cudaGetSymbolAddress((void**)&p_wc,   g_wch);
    cudaGetSymbolAddress((void**)&p_cnt,  g_cnt);

    cudaFuncSetAttribute(k_layer,
                         cudaFuncAttributeMaxDynamicSharedMemorySize, SM_TOT);

    const int SCAN_NB = (NN + 1023) / 1024;
    const int GB = (NN + 127) / 128;

    // conversions + CSR build
    k_tohalf<<<(NN * 32 + 255) / 256, 256>>>(x);
    k_convw<<<(98304 + 255) / 256, 256>>>(W_l0, W_r0, W_l1, W_r1, W_c);
    cudaMemsetAsync(p_cnt, 0, (NN + 1) * sizeof(int));
    k_count<<<(NE + 255) / 256, 256>>>(ei);
    k_scan_block<<<SCAN_NB, 1024>>>();
    k_scan_add<<<SCAN_NB, 1024>>>();
    k_fill<<<(NE + 255) / 256, 256>>>(ei);

    // layer 0 (fused dual GEMM, h SMEM-only)
    k_aggregate<<<(NN + 7) / 8, 256>>>(p_xh, p_mean);
    k_layer<<<GB, 256, SM_TOT>>>(p_xh, p_mean, p_wl0, p_wr0, p_wc,
                                 b_l0, b_c, p_x1, NN);

    // layer 1
    k_aggregate<<<(NN + 7) / 8, 256>>>(p_x1, p_mean);
    k_layer<<<GB, 256, SM_TOT>>>(p_x1, p_mean, p_wl1, p_wr1, p_wc,
                                 b_l1, b_c, p_x2, NN);

    // edge head via linearity: out = (P + b_o)[src] + Q[dst]
    k_pq<<<GB, 256>>>(p_x2, W_o, b_o);
    k_edge<<<(4 * NE + 255) / 256, 256>>>(ei, out);
}

// round 13
// speedup vs baseline: 3.2530x; 1.0445x over previous
#include <cuda_runtime.h>
#include <cuda_fp16.h>
#include <cstdint>

#define NN 100000
#define NE 1000000
#define D  128

// ---------------- scratch (device globals; no allocations allowed) ----------
__device__ int    g_cnt[NN + 1];
__device__ int    g_off[NN + 2];
__device__ int    g_pos[NN];
__device__ int    g_srcs[NE];
__device__ int    g_part[128];
__device__ __half g_xh   [(size_t)NN * D];   // fp16 copy of input x
__device__ __half g_meanh[(size_t)NN * D];
__device__ __half g_x1h  [(size_t)NN * D];
__device__ __half g_P    [(size_t)NN * 16];  // fp16, P + b_o folded
__device__ __half g_Q    [(size_t)NN * 16];  // fp16
// fp16 weights (pre-converted once per call)
__device__ __half g_wl0h[128 * 128];
__device__ __half g_wr0h[128 * 128];
__device__ __half g_wl1h[128 * 128];
__device__ __half g_wr1h[128 * 128];
__device__ __half g_wch [128 * 256];
__device__ __half g_woh [32 * 128];          // rearranged: r<16 = Wo[r][0:128], r>=16 = Wo[r-16][128:256]

// ---------------- helpers ----------------------------------------------------
__device__ __forceinline__ uint32_t smem_u32(const void* p) {
    uint32_t a;
    asm("{ .reg .u64 t; cvta.to.shared.u64 t, %1; cvt.u32.u64 %0, t; }"
        : "=r"(a) : "l"(p));
    return a;
}
__device__ __forceinline__ uint32_t pkh(float lo, float hi) {
    uint32_t d;  // bits[15:0]=f16(lo), bits[31:16]=f16(hi)
    asm("cvt.rn.f16x2.f32 %0, %1, %2;" : "=r"(d) : "f"(hi), "f"(lo));
    return d;
}
__device__ __forceinline__ void ldsm4(uint32_t* r, uint32_t addr) {
    asm volatile("ldmatrix.sync.aligned.m8n8.x4.shared.b16 {%0,%1,%2,%3}, [%4];"
                 : "=r"(r[0]), "=r"(r[1]), "=r"(r[2]), "=r"(r[3]) : "r"(addr));
}
__device__ __forceinline__ void mma_f16(float* d, const uint32_t* a,
                                        const uint32_t* b) {
    asm volatile(
        "mma.sync.aligned.m16n8k16.row.col.f32.f16.f16.f32 "
        "{%0,%1,%2,%3}, {%4,%5,%6,%7}, {%8,%9}, {%0,%1,%2,%3};"
        : "+f"(d[0]), "+f"(d[1]), "+f"(d[2]), "+f"(d[3])
        : "r"(a[0]), "r"(a[1]), "r"(a[2]), "r"(a[3]), "r"(b[0]), "r"(b[1]));
}

// ---------------- prep: x->fp16, all weights->fp16, zero counters ------------
__global__ void k_prep(const float* __restrict__ x,
                       const float* __restrict__ wl0, const float* __restrict__ wr0,
                       const float* __restrict__ wl1, const float* __restrict__ wr1,
                       const float* __restrict__ wc,  const float* __restrict__ wo) {
    int i = blockIdx.x * blockDim.x + threadIdx.x;
    if (i < NN * 32) {           // x: one float4 -> 4 halves
        float4 v = reinterpret_cast<const float4*>(x)[i];
        uint2 h;
        h.x = pkh(v.x, v.y);
        h.y = pkh(v.z, v.w);
        reinterpret_cast<uint2*>(g_xh)[i] = h;
    }
    if (i < 16384)       g_wl0h[i]         = __float2half(wl0[i]);
    else if (i < 32768)  g_wr0h[i - 16384] = __float2half(wr0[i - 16384]);
    else if (i < 49152)  g_wl1h[i - 32768] = __float2half(wl1[i - 32768]);
    else if (i < 65536)  g_wr1h[i - 49152] = __float2half(wr1[i - 49152]);
    else if (i < 98304)  g_wch[i - 65536]  = __float2half(wc[i - 65536]);
    else if (i < 102400) {       // Wo rearranged to [32,128]
        int j = i - 98304;
        int r = j >> 7, c = j & 127;
        float v = (r < 16) ? wo[(size_t)r * 256 + c]
                           : wo[(size_t)(r - 16) * 256 + 128 + c];
        g_woh[j] = __float2half(v);
    }
    if (i <= NN) g_cnt[i] = 0;
}

// ---------------- CSR build (edge_index is int32: JAX x64 disabled) ----------
__global__ void k_count(const int* __restrict__ ei) {
    int e = blockIdx.x * blockDim.x + threadIdx.x;
    if (e < NE) {
        unsigned d = (unsigned)ei[NE + e];
        if (d < NN) atomicAdd(&g_cnt[d], 1);
    }
}

__global__ void k_scan_block() {   // per-block exclusive scan of g_cnt -> g_off
    __shared__ int sh[1024];
    int i = blockIdx.x * 1024 + threadIdx.x;
    int v = (i < NN) ? g_cnt[i] : 0;
    sh[threadIdx.x] = v;
    __syncthreads();
    for (int off = 1; off < 1024; off <<= 1) {
        int t = (threadIdx.x >= off) ? sh[threadIdx.x - off] : 0;
        __syncthreads();
        sh[threadIdx.x] += t;
        __syncthreads();
    }
    if (i < NN) g_off[i] = sh[threadIdx.x] - v;   // exclusive
    if (threadIdx.x == 1023) g_part[blockIdx.x] = sh[1023];
}

__global__ void k_scan_add() {   // parallel scan over block partials
    __shared__ int sp[128];
    int b = blockIdx.x;
    int nb = gridDim.x;
    if (threadIdx.x < 128)
        sp[threadIdx.x] = (threadIdx.x < nb) ? g_part[threadIdx.x] : 0;
    __syncthreads();
    for (int off = 1; off < 128; off <<= 1) {
        int t = 0;
        if (threadIdx.x < 128 && threadIdx.x >= off) t = sp[threadIdx.x - off];
        __syncthreads();
        if (threadIdx.x < 128) sp[threadIdx.x] += t;
        __syncthreads();
    }
    int s_base = (b == 0) ? 0 : sp[b - 1];
    int i = b * 1024 + threadIdx.x;
    if (i < NN) {
        int o = g_off[i] + s_base;
        g_off[i] = o;
        g_pos[i] = o;
    }
    if (i == 0) g_off[NN] = NE;
}

__global__ void k_fill(const int* __restrict__ ei) {
    int e = blockIdx.x * blockDim.x + threadIdx.x;
    if (e < NE) {
        unsigned d = (unsigned)ei[NE + e];
        if (d < NN) {
            int p = atomicAdd(&g_pos[d], 1);
            if (p >= 0 && p < NE) g_srcs[p] = ei[e];
        }
    }
}

// ---------------- mean aggregation (fp16 rows): one warp per node ------------
__global__ void k_aggregate(const __half* __restrict__ xin,
                            __half* __restrict__ mout) {
    int n = blockIdx.x * (blockDim.x >> 5) + (threadIdx.x >> 5);
    if (n >= NN) return;
    int lane = threadIdx.x & 31;
    int beg = g_off[n], end = g_off[n + 1];
    float ax = 0.f, ay = 0.f, az = 0.f, aw = 0.f;
    #pragma unroll 4
    for (int t = beg; t < end; t++) {
        unsigned s = (unsigned)g_srcs[t];
        if (s >= NN) continue;
        uint2 v = *reinterpret_cast<const uint2*>(xin + (size_t)s * D + lane * 4);
        __half2 h0 = *reinterpret_cast<__half2*>(&v.x);
        __half2 h1 = *reinterpret_cast<__half2*>(&v.y);
        float2 f0 = __half22float2(h0), f1 = __half22float2(h1);
        ax += f0.x; ay += f0.y; az += f1.x; aw += f1.y;
    }
    int c = end - beg;
    float inv = 1.0f / (float)(c > 0 ? c : 1);
    uint2 o;
    o.x = pkh(ax * inv, ay * inv);
    o.y = pkh(az * inv, aw * inv);
    *reinterpret_cast<uint2*>(mout + (size_t)n * D + lane * 4) = o;
}

// ---------------- fused SAGE layer (+ optional fused P/Q head) ---------------
// h = relu([mean|x]W^T + bl) (SMEM only); x' = relu([x|h]Wc^T + bc).
// do_pq=0: write x' to OUT. do_pq=1: x' -> SMEM, then P/Q = x' x Wo^T (+b_o).
#define SROW   272
#define SX_OFF 0
#define SMH_OFF 34816
#define SB_OFF 69632
#define SM_TOT 104448

struct MmaCtx {
    uint32_t smb, aoff, boff;
    int m0, n0;
};

__device__ __forceinline__ void mma_tiles(const MmaCtx& c, uint32_t a_off_base,
                                          float acc[2][8][4]) {
    #pragma unroll
    for (int ks = 0; ks < 8; ks++) {
        uint32_t a0[4], a1[4], bf[4][4];
        ldsm4(a0, c.smb + a_off_base + (uint32_t)(c.m0 * SROW) + ks * 32 + c.aoff);
        ldsm4(a1, c.smb + a_off_base + (uint32_t)((c.m0 + 16) * SROW) + ks * 32 + c.aoff);
        #pragma unroll
        for (int nb = 0; nb < 4; nb++)
            ldsm4(bf[nb], c.smb + SB_OFF + (uint32_t)((c.n0 + nb * 16) * SROW)
                          + ks * 32 + c.boff);
        #pragma unroll
        for (int nb = 0; nb < 4; nb++) {
            mma_f16(acc[0][nb * 2 + 0], a0, &bf[nb][0]);
            mma_f16(acc[0][nb * 2 + 1], a0, &bf[nb][2]);
            mma_f16(acc[1][nb * 2 + 0], a1, &bf[nb][0]);
            mma_f16(acc[1][nb * 2 + 1], a1, &bf[nb][2]);
        }
    }
}

__device__ __forceinline__ void load_b(char* sm, const __half* __restrict__ w,
                                       int stride, int tid) {
    #pragma unroll
    for (int i = 0; i < 8; i++) {
        int idx = tid + i * 256;          // 0..2047
        int r = idx >> 4, cc = idx & 15;
        uint4 v = *reinterpret_cast<const uint4*>(w + (size_t)r * stride + cc * 8);
        *reinterpret_cast<uint4*>(sm + SB_OFF + r * SROW + cc * 16) = v;
    }
}

__global__ void __launch_bounds__(256, 2) k_layer(
    const __half* __restrict__ X, const __half* __restrict__ MEAN,
    const __half* __restrict__ Wl, const __half* __restrict__ Wr,
    const __half* __restrict__ Wc, const __half* __restrict__ Wo,
    const float* __restrict__ bl, const float* __restrict__ bc,
    const float* __restrict__ bo,
    __half* __restrict__ OUT, int nrows, int do_pq)
{
    extern __shared__ __align__(16) char sm[];
    uint32_t smb = smem_u32(sm);
    int tid = threadIdx.x, lane = tid & 31, wid = tid >> 5;
    int row0 = blockIdx.x * 128;

    MmaCtx c;
    c.smb = smb;
    c.m0 = (wid >> 1) * 32;
    c.n0 = (wid & 1) * 64;
    {
        int t = lane >> 3, rr = lane & 7;
        c.aoff = (uint32_t)((lane & 15) * SROW + (lane >> 4) * 16);
        c.boff = (uint32_t)((((t >> 1) * 8 + rr) * SROW) + (t & 1) * 16);
    }

    // load x and mean tiles (fp16 straight copies)
    #pragma unroll
    for (int i = 0; i < 8; i++) {
        int idx = tid + i * 256;
        int r = idx >> 4, cc = idx & 15;
        int gr = row0 + r;
        uint4 vx = make_uint4(0u, 0u, 0u, 0u), vm = vx;
        if (gr < nrows) {
            vx = *reinterpret_cast<const uint4*>(X + (size_t)gr * D + cc * 8);
            vm = *reinterpret_cast<const uint4*>(MEAN + (size_t)gr * D + cc * 8);
        }
        *reinterpret_cast<uint4*>(sm + SX_OFF + r * SROW + cc * 16) = vx;
        *reinterpret_cast<uint4*>(sm + SMH_OFF + r * SROW + cc * 16) = vm;
    }
    load_b(sm, Wl, 128, tid);
    __syncthreads();

    float acc[2][8][4];
    #pragma unroll
    for (int i = 0; i < 2; i++)
        #pragma unroll
        for (int j = 0; j < 8; j++)
            #pragma unroll
            for (int q = 0; q < 4; q++) acc[i][j][q] = 0.f;

    // GEMM1 phase a: mean x Wl
    mma_tiles(c, SMH_OFF, acc);
    __syncthreads();
    load_b(sm, Wr, 128, tid);
    __syncthreads();
    // GEMM1 phase b: x x Wr
    mma_tiles(c, SX_OFF, acc);

    // epilogue 1: h = relu(acc + bl) -> SMEM (overwrites mean tile)
    #pragma unroll
    for (int mi = 0; mi < 2; mi++) {
        int r0 = c.m0 + mi * 16 + (lane >> 2);
        #pragma unroll
        for (int f = 0; f < 8; f++) {
            int col = c.n0 + f * 8 + (lane & 3) * 2;
            float2 bv = *reinterpret_cast<const float2*>(bl + col);
            uint32_t h0 = pkh(fmaxf(acc[mi][f][0] + bv.x, 0.f),
                              fmaxf(acc[mi][f][1] + bv.y, 0.f));
            uint32_t h1 = pkh(fmaxf(acc[mi][f][2] + bv.x, 0.f),
                              fmaxf(acc[mi][f][3] + bv.y, 0.f));
            *reinterpret_cast<uint32_t*>(sm + SMH_OFF + r0 * SROW + col * 2) = h0;
            *reinterpret_cast<uint32_t*>(sm + SMH_OFF + (r0 + 8) * SROW + col * 2) = h1;
        }
    }
    __syncthreads();
    load_b(sm, Wc, 256, tid);          // Wc k-cols [0,128) -> multiplies x
    __syncthreads();

    #pragma unroll
    for (int i = 0; i < 2; i++)
        #pragma unroll
        for (int j = 0; j < 8; j++)
            #pragma unroll
            for (int q = 0; q < 4; q++) acc[i][j][q] = 0.f;

    // GEMM2 phase a: x x Wc1
    mma_tiles(c, SX_OFF, acc);
    __syncthreads();
    load_b(sm, Wc + 128, 256, tid);    // Wc k-cols [128,256) -> multiplies h
    __syncthreads();
    // GEMM2 phase b: h x Wc2
    mma_tiles(c, SMH_OFF, acc);

    if (!do_pq) {
        // epilogue 2: x' = relu(acc + bc) -> global fp16
        #pragma unroll
        for (int mi = 0; mi < 2; mi++) {
            int gr0 = row0 + c.m0 + mi * 16 + (lane >> 2);
            #pragma unroll
            for (int f = 0; f < 8; f++) {
                int col = c.n0 + f * 8 + (lane & 3) * 2;
                float2 bv = *reinterpret_cast<const float2*>(bc + col);
                if (gr0 < nrows) {
                    uint32_t h = pkh(fmaxf(acc[mi][f][0] + bv.x, 0.f),
                                     fmaxf(acc[mi][f][1] + bv.y, 0.f));
                    *reinterpret_cast<uint32_t*>(OUT + (size_t)gr0 * D + col) = h;
                }
                if (gr0 + 8 < nrows) {
                    uint32_t h = pkh(fmaxf(acc[mi][f][2] + bv.x, 0.f),
                                     fmaxf(acc[mi][f][3] + bv.y, 0.f));
                    *reinterpret_cast<uint32_t*>(OUT + (size_t)(gr0 + 8) * D + col) = h;
                }
            }
        }
        return;
    }

    // ---- fused P/Q head: x' -> SMEM (SX region), then [128x128] x Wo^T -----
    __syncthreads();   // all GEMM2b reads of SX-era data done (SX last read in GEMM2a; B region free next)
    #pragma unroll
    for (int mi = 0; mi < 2; mi++) {
        int r0 = c.m0 + mi * 16 + (lane >> 2);
        #pragma unroll
        for (int f = 0; f < 8; f++) {
            int col = c.n0 + f * 8 + (lane & 3) * 2;
            float2 bv = *reinterpret_cast<const float2*>(bc + col);
            uint32_t h0 = pkh(fmaxf(acc[mi][f][0] + bv.x, 0.f),
                              fmaxf(acc[mi][f][1] + bv.y, 0.f));
            uint32_t h1 = pkh(fmaxf(acc[mi][f][2] + bv.x, 0.f),
                              fmaxf(acc[mi][f][3] + bv.y, 0.f));
            *reinterpret_cast<uint32_t*>(sm + SX_OFF + r0 * SROW + col * 2) = h0;
            *reinterpret_cast<uint32_t*>(sm + SX_OFF + (r0 + 8) * SROW + col * 2) = h1;
        }
    }
    // Wo tile: 32 rows x 128 halves
    #pragma unroll
    for (int i = 0; i < 2; i++) {
        int idx = tid + i * 256;          // 0..511
        int r = idx >> 4, cc = idx & 15;
        uint4 v = *reinterpret_cast<const uint4*>(Wo + (size_t)r * 128 + cc * 8);
        *reinterpret_cast<uint4*>(sm + SB_OFF + r * SROW + cc * 16) = v;
    }
    __syncthreads();

    int m0 = wid * 16;
    float pq[4][4];
    #pragma unroll
    for (int j = 0; j < 4; j++)
        #pragma unroll
        for (int q = 0; q < 4; q++) pq[j][q] = 0.f;

    #pragma unroll
    for (int ks = 0; ks < 8; ks++) {
        uint32_t a0[4], bf[2][4];
        ldsm4(a0, smb + SX_OFF + (uint32_t)(m0 * SROW) + ks * 32 + c.aoff);
        ldsm4(bf[0], smb + SB_OFF + ks * 32 + c.boff);
        ldsm4(bf[1], smb + SB_OFF + (uint32_t)(16 * SROW) + ks * 32 + c.boff);
        mma_f16(pq[0], a0, &bf[0][0]);
        mma_f16(pq[1], a0, &bf[0][2]);
        mma_f16(pq[2], a0, &bf[1][0]);
        mma_f16(pq[3], a0, &bf[1][2]);
    }

    // epilogue: cols 0..15 -> P (+= b_o, fp16), cols 16..31 -> Q (fp16)
    int gr0 = row0 + m0 + (lane >> 2);
    #pragma unroll
    for (int f = 0; f < 4; f++) {
        int col = f * 8 + (lane & 3) * 2;   // 0..30
        #pragma unroll
        for (int half = 0; half < 2; half++) {
            int gr = gr0 + half * 8;
            if (gr >= nrows) continue;
            float vx = pq[f][half * 2 + 0];
            float vy = pq[f][half * 2 + 1];
            if (col < 16) {
                float2 bv = *reinterpret_cast<const float2*>(bo + col);
                uint32_t h = pkh(vx + bv.x, vy + bv.y);
                *reinterpret_cast<uint32_t*>(g_P + (size_t)gr * 16 + col) = h;
            } else {
                uint32_t h = pkh(vx, vy);
                *reinterpret_cast<uint32_t*>(g_Q + (size_t)gr * 16 + (col - 16)) = h;
            }
        }
    }
}

// ---------------- edge head: out[e] = P'[src] + Q[dst] (fp16 rows) -----------
__global__ void k_edge(const int* __restrict__ ei, float* __restrict__ out) {
    int t = blockIdx.x * blockDim.x + threadIdx.x;
    if (t >= NE * 2) return;
    int e = t >> 1, q = t & 1;           // q: which 8-class half
    unsigned s = (unsigned)ei[e];
    unsigned d = (unsigned)ei[NE + e];
    uint4 ph = make_uint4(0u, 0u, 0u, 0u), qh = ph;
    if (s < NN) ph = *reinterpret_cast<const uint4*>(g_P + (size_t)s * 16 + q * 8);
    if (d < NN) qh = *reinterpret_cast<const uint4*>(g_Q + (size_t)d * 16 + q * 8);
    float4 o0, o1;
    {
        float2 p0 = __half22float2(*reinterpret_cast<__half2*>(&ph.x));
        float2 p1 = __half22float2(*reinterpret_cast<__half2*>(&ph.y));
        float2 p2 = __half22float2(*reinterpret_cast<__half2*>(&ph.z));
        float2 p3 = __half22float2(*reinterpret_cast<__half2*>(&ph.w));
        float2 q0 = __half22float2(*reinterpret_cast<__half2*>(&qh.x));
        float2 q1 = __half22float2(*reinterpret_cast<__half2*>(&qh.y));
        float2 q2 = __half22float2(*reinterpret_cast<__half2*>(&qh.z));
        float2 q3 = __half22float2(*reinterpret_cast<__half2*>(&qh.w));
        o0.x = p0.x + q0.x; o0.y = p0.y + q0.y;
        o0.z = p1.x + q1.x; o0.w = p1.y + q1.y;
        o1.x = p2.x + q2.x; o1.y = p2.y + q2.y;
        o1.z = p3.x + q3.x; o1.w = p3.y + q3.y;
    }
    float4* dst = reinterpret_cast<float4*>(out) + (size_t)e * 4 + q * 2;
    __stcs(dst, o0);
    __stcs(dst + 1, o1);
}

// ---------------- launch -----------------------------------------------------
extern "C" void kernel_launch(void* const* d_in, const int* in_sizes, int n_in,
                              void* d_out, int out_size) {
    const float* x    = (const float*)d_in[0];
    const int*   ei   = (const int*)d_in[1];     // int32: JAX x64 is disabled
    const float* W_l0 = (const float*)d_in[2];
    const float* b_l0 = (const float*)d_in[3];
    const float* W_r0 = (const float*)d_in[4];
    const float* W_l1 = (const float*)d_in[5];
    const float* b_l1 = (const float*)d_in[6];
    const float* W_r1 = (const float*)d_in[7];
    const float* W_c  = (const float*)d_in[8];
    const float* b_c  = (const float*)d_in[9];
    const float* W_o  = (const float*)d_in[10];
    const float* b_o  = (const float*)d_in[11];
    float*       out  = (float*)d_out;

    __half *p_xh, *p_mean, *p_x1;
    __half *p_wl0, *p_wr0, *p_wl1, *p_wr1, *p_wc, *p_wo;
    cudaGetSymbolAddress((void**)&p_xh,   g_xh);
    cudaGetSymbolAddress((void**)&p_mean, g_meanh);
    cudaGetSymbolAddress((void**)&p_x1,   g_x1h);
    cudaGetSymbolAddress((void**)&p_wl0,  g_wl0h);
    cudaGetSymbolAddress((void**)&p_wr0,  g_wr0h);
    cudaGetSymbolAddress((void**)&p_wl1,  g_wl1h);
    cudaGetSymbolAddress((void**)&p_wr1,  g_wr1h);
    cudaGetSymbolAddress((void**)&p_wc,   g_wch);
    cudaGetSymbolAddress((void**)&p_wo,   g_woh);

    cudaFuncSetAttribute(k_layer,
                         cudaFuncAttributeMaxDynamicSharedMemorySize, SM_TOT);

    const int SCAN_NB = (NN + 1023) / 1024;
    const int GB = (NN + 127) / 128;

    // launch 1: prep (x->fp16, weights->fp16, counters zeroed)
    k_prep<<<(NN * 32 + 255) / 256, 256>>>(x, W_l0, W_r0, W_l1, W_r1, W_c, W_o);
    // launches 2-5: CSR build
    k_count<<<(NE + 255) / 256, 256>>>(ei);
    k_scan_block<<<SCAN_NB, 1024>>>();
    k_scan_add<<<SCAN_NB, 1024>>>();
    k_fill<<<(NE + 255) / 256, 256>>>(ei);

    // launch 6: aggregate (ncu -s 5 window lands here)
    k_aggregate<<<(NN + 7) / 8, 256>>>(p_xh, p_mean);
    // layer 0
    k_layer<<<GB, 256, SM_TOT>>>(p_xh, p_mean, p_wl0, p_wr0, p_wc, p_wo,
                                 b_l0, b_c, b_o, p_x1, NN, 0);
    // layer 1 (+ fused P/Q head)
    k_aggregate<<<(NN + 7) / 8, 256>>>(p_x1, p_mean);
    k_layer<<<GB, 256, SM_TOT>>>(p_x1, p_mean, p_wl1, p_wr1, p_wc, p_wo,
                                 b_l1, b_c, b_o, p_x1, NN, 1);

    // edge head: out = (P + b_o)[src] + Q[dst]
    k_edge<<<(2 * NE + 255) / 256, 256>>>(ei, out);
}